// round 10
// baseline (speedup 1.0000x reference)
#include <cuda_runtime.h>
#include <cuda_fp16.h>
#include <math.h>
#include <stdint.h>

#define E_DIM 1024
#define H_DIM 16
#define D_DIM 64
#define S_LEN 1024
#define N_B   4
#define L_NUM 4
#define FF_DIM 4096
#define V_DIM 32000
#define M_TOK (N_B * S_LEN)   // 4096 token rows
#define QKV_STR (3 * E_DIM)   // 3072

// ---------------------------------------------------------------------------
// Transposed-weight half buffer layout (element offsets)
// ---------------------------------------------------------------------------
#define QKV_LSTR   (3 * E_DIM * E_DIM)
#define OFF_WO     (L_NUM * QKV_LSTR)
#define WO_LSTR    (E_DIM * E_DIM)
#define OFF_W1     (OFF_WO + L_NUM * WO_LSTR)
#define W1_LSTR    (E_DIM * FF_DIM)
#define OFF_W2     (OFF_W1 + L_NUM * W1_LSTR)
#define W2_LSTR    (FF_DIM * E_DIM)
#define OFF_WOUT   (OFF_W2 + L_NUM * W2_LSTR)
#define WH_TOTAL   (OFF_WOUT + (size_t)V_DIM * E_DIM)

// ---------------------------------------------------------------------------
// Scratch (device globals; no allocations allowed)
// ---------------------------------------------------------------------------
__device__ float  g_act  [M_TOK * E_DIM];
__device__ __half g_act_h[M_TOK * E_DIM];
__device__ float  g_qkv  [M_TOK * QKV_STR];
__device__ __half g_attn_h[M_TOK * E_DIM];
__device__ float  g_tmp  [M_TOK * E_DIM];
__device__ float  g_h    [M_TOK * E_DIM];
__device__ __half g_h_h  [M_TOK * E_DIM];
__device__ __half g_ff_h [M_TOK * FF_DIM];
__device__ float  g_bqkv [L_NUM * QKV_STR];
__device__ __half g_wh   [WH_TOTAL];

__device__ __forceinline__ uint32_t f2tf32(float x) {
    uint32_t r;
    asm("cvt.rna.tf32.f32 %0, %1;" : "=r"(r) : "f"(x));
    return r;
}

__device__ __forceinline__ uint32_t smem_u32(const void* p) {
    uint32_t a;
    asm("{ .reg .u64 t; cvta.to.shared.u64 t, %1; cvt.u32.u64 %0, t; }"
        : "=r"(a) : "l"(p));
    return a;
}

__device__ __forceinline__ void ldsm_x4(uint32_t* r, uint32_t addr) {
    asm volatile("ldmatrix.sync.aligned.m8n8.x4.shared.b16 {%0,%1,%2,%3}, [%4];"
                 : "=r"(r[0]), "=r"(r[1]), "=r"(r[2]), "=r"(r[3]) : "r"(addr));
}
__device__ __forceinline__ void ldsm_x2(uint32_t* r, uint32_t addr) {
    asm volatile("ldmatrix.sync.aligned.m8n8.x2.shared.b16 {%0,%1}, [%2];"
                 : "=r"(r[0]), "=r"(r[1]) : "r"(addr));
}

// ---------------------------------------------------------------------------
// Embedding + sinusoidal positional encoding (writes f32 + half copies)
// ---------------------------------------------------------------------------
__global__ void embed_kernel(const int* __restrict__ x,
                             const float* __restrict__ emb,
                             float* __restrict__ out,
                             __half* __restrict__ outh)
{
    int row = blockIdx.x;
    int s   = row & (S_LEN - 1);
    int tok = x[row];
    const float* erow = emb + (size_t)tok * E_DIM;
    float* orow = out + (size_t)row * E_DIM;
    __half* ohrow = outh + (size_t)row * E_DIM;

    int e0 = threadIdx.x * 4;
    #pragma unroll
    for (int j = 0; j < 4; j++) {
        int e = e0 + j;
        int even = e & ~1;
        float expo = (float)even / (float)E_DIM;
        float denom = powf(10000.0f, expo);
        float ang = (float)s / denom;
        float pe = (e & 1) ? cosf(ang) : sinf(ang);
        float v = erow[e] + pe;
        orow[e] = v;
        ohrow[e] = __float2half_rn(v);
    }
}

// ---------------------------------------------------------------------------
// Batched transpose+half: Dz[n][k] = half(Wz[k][n])
// ---------------------------------------------------------------------------
__global__ __launch_bounds__(256)
void transpose_half_b(const float* __restrict__ W, __half* __restrict__ dst,
                      int Kd, int Nd, size_t src_stride, size_t dst_stride)
{
    __shared__ float tile[32][33];
    const float* Wz = W + (size_t)blockIdx.z * src_stride;
    __half* Dz = dst + (size_t)blockIdx.z * dst_stride;
    int n0 = blockIdx.x * 32, k0 = blockIdx.y * 32;
    int tx = threadIdx.x, ty = threadIdx.y;
    #pragma unroll
    for (int dy = 0; dy < 32; dy += 8)
        tile[ty + dy][tx] = Wz[(size_t)(k0 + ty + dy) * Nd + n0 + tx];
    __syncthreads();
    #pragma unroll
    for (int dy = 0; dy < 32; dy += 8)
        Dz[(size_t)(n0 + ty + dy) * Kd + k0 + tx] =
            __float2half_rn(tile[tx][ty + dy]);
}

__global__ void pack_qkv_bias(const float* __restrict__ bq,
                              const float* __restrict__ bk,
                              const float* __restrict__ bv,
                              float* __restrict__ out)
{
    int i = blockIdx.x * 256 + threadIdx.x;
    int layer = i / QKV_STR, c = i % QKV_STR;
    float v;
    if (c < E_DIM)           v = bq[layer * E_DIM + c];
    else if (c < 2 * E_DIM)  v = bk[layer * E_DIM + c - E_DIM];
    else                     v = bv[layer * E_DIM + c - 2 * E_DIM];
    out[i] = v;
}

// ---------------------------------------------------------------------------
// FP16 GEMM: round-6 proven shape (CTA 128x128, warp 64x32, double buffer,
// 2 CTAs/SM) with half A via cp.async and BK=64.
// A[M][K] half, Bt[N][K] half. f32 accum. ROWB=144 (9*16, conflict-free).
// ---------------------------------------------------------------------------
#define GBM 128
#define GBN 128
#define GBK 64
#define ROWB 144
#define A_ST (128 * ROWB)            // 18432
#define STG  (2 * A_ST)              // 36864 (A + B)
#define GEMM_SMEM (2 * STG)          // 73728

template<int RELU, int WF, int WH>
__global__ __launch_bounds__(256, 2)
void hgemm3(const __half* __restrict__ A, const __half* __restrict__ Bt,
            const float* __restrict__ bias,
            float* __restrict__ Cf, __half* __restrict__ Ch,
            int Nd, int Kd)
{
    extern __shared__ char smem[];
    const uint32_t sbase = smem_u32(smem);

    const int tid  = threadIdx.x;
    const int lane = tid & 31;
    const int wid  = tid >> 5;
    const int gid  = lane >> 2;
    const int tig  = lane & 3;

    const int m0 = blockIdx.y * GBM;
    const int n0 = blockIdx.x * GBN;
    const int wm = (wid >> 2) * 64;
    const int wn = (wid & 3) * 32;

    const int arow = wm + (lane & 15);
    const int akoh = (lane & 16) ? 8 : 0;
    const int brow = wn + (lane & 7);
    const int bkoh = (lane & 8) ? 8 : 0;

    // staging: 128 rows x 128B data per operand; 256 thr x 16B -> 4 issues each
    const int s_r = tid >> 1;        // 0..127 row (two threads per row)
    const int s_q = tid & 1;         // 16B chunk pair base

    float acc[4][4][4];
    #pragma unroll
    for (int i = 0; i < 4; i++)
        #pragma unroll
        for (int j = 0; j < 4; j++)
            #pragma unroll
            for (int r = 0; r < 4; r++) acc[i][j][r] = 0.0f;

    const int nK = Kd / GBK;

    auto issue_stage = [&](int t, int buf) {
        const uint32_t base = sbase + buf * STG;
        const __half* Ag = A + (size_t)m0 * Kd + t * GBK;
        const __half* Bg = Bt + (size_t)n0 * Kd + t * GBK;
        #pragma unroll
        for (int p = 0; p < 4; p++) {
            int q = s_q + ((p & 1) * 2) + ((p >> 1) * 4);  // 0..7 16B chunks
            uint32_t da = base + s_r * ROWB + q * 16;
            const __half* sa = Ag + (size_t)s_r * Kd + q * 8;
            asm volatile("cp.async.cg.shared.global [%0], [%1], 16;\n"
                         :: "r"(da), "l"(sa));
            uint32_t db = base + A_ST + s_r * ROWB + q * 16;
            const __half* sb = Bg + (size_t)s_r * Kd + q * 8;
            asm volatile("cp.async.cg.shared.global [%0], [%1], 16;\n"
                         :: "r"(db), "l"(sb));
        }
        asm volatile("cp.async.commit_group;\n");
    };

    issue_stage(0, 0);
    asm volatile("cp.async.wait_group 0;\n");
    __syncthreads();

    for (int t = 0; t < nK; t++) {
        const int cur = t & 1;
        const bool has_next = (t + 1 < nK);
        if (has_next) issue_stage(t + 1, cur ^ 1);

        const uint32_t sA = sbase + cur * STG;
        const uint32_t sB = sA + A_ST;
        #pragma unroll
        for (int ko = 0; ko < GBK; ko += 16) {
            uint32_t af[4][4], bf[4][2];
            #pragma unroll
            for (int mt = 0; mt < 4; mt++)
                ldsm_x4(af[mt], sA + (arow + mt * 16) * ROWB + (ko + akoh) * 2);
            #pragma unroll
            for (int nt = 0; nt < 4; nt++)
                ldsm_x2(bf[nt], sB + (brow + nt * 8) * ROWB + (ko + bkoh) * 2);
            #pragma unroll
            for (int mt = 0; mt < 4; mt++)
                #pragma unroll
                for (int nt = 0; nt < 4; nt++) {
                    asm volatile(
                        "mma.sync.aligned.m16n8k16.row.col.f32.f16.f16.f32 "
                        "{%0,%1,%2,%3}, {%4,%5,%6,%7}, {%8,%9}, {%0,%1,%2,%3};\n"
                        : "+f"(acc[mt][nt][0]), "+f"(acc[mt][nt][1]),
                          "+f"(acc[mt][nt][2]), "+f"(acc[mt][nt][3])
                        : "r"(af[mt][0]), "r"(af[mt][1]),
                          "r"(af[mt][2]), "r"(af[mt][3]),
                          "r"(bf[nt][0]), "r"(bf[nt][1]));
                }
        }

        if (has_next) asm volatile("cp.async.wait_group 0;\n");
        __syncthreads();
    }

    // epilogue
    #pragma unroll
    for (int nt = 0; nt < 4; nt++) {
        int col = n0 + wn + nt * 8 + 2 * tig;
        float b0 = bias[col];
        float b1 = bias[col + 1];
        #pragma unroll
        for (int mt = 0; mt < 4; mt++) {
            int row = m0 + wm + mt * 16 + gid;
            float v00 = acc[mt][nt][0] + b0;
            float v01 = acc[mt][nt][1] + b1;
            float v10 = acc[mt][nt][2] + b0;
            float v11 = acc[mt][nt][3] + b1;
            if (RELU) {
                v00 = fmaxf(v00, 0.0f); v01 = fmaxf(v01, 0.0f);
                v10 = fmaxf(v10, 0.0f); v11 = fmaxf(v11, 0.0f);
            }
            if (WF) {
                float2 f0 = {v00, v01}, f1 = {v10, v11};
                *(float2*)(Cf + (size_t)row * Nd + col)       = f0;
                *(float2*)(Cf + (size_t)(row + 8) * Nd + col) = f1;
            }
            if (WH) {
                __half2 h0 = __floats2half2_rn(v00, v01);
                __half2 h1 = __floats2half2_rn(v10, v11);
                *(__half2*)(Ch + (size_t)row * Nd + col)       = h0;
                *(__half2*)(Ch + (size_t)(row + 8) * Nd + col) = h1;
            }
        }
    }
}

// ---------------------------------------------------------------------------
// Flash attention (tf32 mma.sync); reads fused QKV f32, writes half O.
// ---------------------------------------------------------------------------
#define QSTR 68
#define KSTR 68
#define VSTR 72
#define PSTR 132
#define ATTN_SMEM ((128*QSTR + 128*KSTR + 128*VSTR + 128*PSTR) * 4)

__global__ __launch_bounds__(256)
void flash_attn(const float* __restrict__ QKV, __half* __restrict__ O)
{
    extern __shared__ float sm[];
    float* Qs = sm;
    float* Ks = Qs + 128 * QSTR;
    float* Vs = Ks + 128 * KSTR;
    float* Ps = Vs + 128 * VSTR;

    const int tid  = threadIdx.x;
    const int lane = tid & 31;
    const int wid  = tid >> 5;
    const int gid  = lane >> 2;
    const int tig  = lane & 3;

    const int qt = gridDim.x - 1 - blockIdx.x;
    const int h  = blockIdx.y;
    const int n  = blockIdx.z;
    const size_t binq = ((size_t)n * S_LEN) * QKV_STR + h * D_DIM;
    const size_t bink = binq + E_DIM;
    const size_t binv = binq + 2 * E_DIM;
    const size_t bout = ((size_t)n * S_LEN) * E_DIM + h * D_DIM;
    const float scale = 1.0f / 32.0f;
    const int wrow = wid * 16;

    #pragma unroll
    for (int l = 0; l < 8; l++) {
        int idx = tid + l * 256;
        int r = idx >> 4, c4 = (idx & 15) * 4;
        float4 v = *(const float4*)(QKV + binq + (size_t)(qt * 128 + r) * QKV_STR + c4);
        uint4 u;
        u.x = f2tf32(v.x * scale); u.y = f2tf32(v.y * scale);
        u.z = f2tf32(v.z * scale); u.w = f2tf32(v.w * scale);
        *(uint4*)(Qs + r * QSTR + c4) = u;
    }

    float accO[8][4];
    #pragma unroll
    for (int i = 0; i < 8; i++)
        #pragma unroll
        for (int j = 0; j < 4; j++) accO[i][j] = 0.0f;
    float m0 = -1e30f, m1 = -1e30f, l0 = 0.0f, l1 = 0.0f;

    const int rbase = wrow + gid;

    for (int kt = 0; kt <= qt; kt++) {
        __syncthreads();
        #pragma unroll
        for (int l = 0; l < 8; l++) {
            int idx = tid + l * 256;
            int r = idx >> 4, c4 = (idx & 15) * 4;
            const size_t roff = (size_t)(kt * 128 + r) * QKV_STR + c4;
            float4 kv = *(const float4*)(QKV + bink + roff);
            uint4 ku;
            ku.x = f2tf32(kv.x); ku.y = f2tf32(kv.y);
            ku.z = f2tf32(kv.z); ku.w = f2tf32(kv.w);
            *(uint4*)(Ks + r * KSTR + c4) = ku;
            float4 vv = *(const float4*)(QKV + binv + roff);
            uint4 vu;
            vu.x = f2tf32(vv.x); vu.y = f2tf32(vv.y);
            vu.z = f2tf32(vv.z); vu.w = f2tf32(vv.w);
            *(uint4*)(Vs + r * VSTR + c4) = vu;
        }
        __syncthreads();

        float accS[16][4];
        #pragma unroll
        for (int i = 0; i < 16; i++)
            #pragma unroll
            for (int j = 0; j < 4; j++) accS[i][j] = 0.0f;

        #pragma unroll
        for (int ks = 0; ks < 8; ks++) {
            uint32_t a0 = *(const uint32_t*)(Qs + (rbase    ) * QSTR + ks * 8 + tig);
            uint32_t a1 = *(const uint32_t*)(Qs + (rbase + 8) * QSTR + ks * 8 + tig);
            uint32_t a2 = *(const uint32_t*)(Qs + (rbase    ) * QSTR + ks * 8 + tig + 4);
            uint32_t a3 = *(const uint32_t*)(Qs + (rbase + 8) * QSTR + ks * 8 + tig + 4);
            #pragma unroll
            for (int nt = 0; nt < 16; nt++) {
                uint32_t b0 = *(const uint32_t*)(Ks + (nt * 8 + gid) * KSTR + ks * 8 + tig);
                uint32_t b1 = *(const uint32_t*)(Ks + (nt * 8 + gid) * KSTR + ks * 8 + tig + 4);
                asm volatile(
                    "mma.sync.aligned.m16n8k8.row.col.f32.tf32.tf32.f32 "
                    "{%0,%1,%2,%3}, {%4,%5,%6,%7}, {%8,%9}, {%0,%1,%2,%3};\n"
                    : "+f"(accS[nt][0]), "+f"(accS[nt][1]),
                      "+f"(accS[nt][2]), "+f"(accS[nt][3])
                    : "r"(a0), "r"(a1), "r"(a2), "r"(a3), "r"(b0), "r"(b1));
            }
        }

        if (kt == qt) {
            #pragma unroll
            for (int nt = 0; nt < 16; nt++) {
                int c = nt * 8 + 2 * tig;
                if (c     > rbase    ) accS[nt][0] = -1e30f;
                if (c + 1 > rbase    ) accS[nt][1] = -1e30f;
                if (c     > rbase + 8) accS[nt][2] = -1e30f;
                if (c + 1 > rbase + 8) accS[nt][3] = -1e30f;
            }
        }

        float mx0 = -1e30f, mx1 = -1e30f;
        #pragma unroll
        for (int nt = 0; nt < 16; nt++) {
            mx0 = fmaxf(mx0, fmaxf(accS[nt][0], accS[nt][1]));
            mx1 = fmaxf(mx1, fmaxf(accS[nt][2], accS[nt][3]));
        }
        mx0 = fmaxf(mx0, __shfl_xor_sync(0xffffffffu, mx0, 1));
        mx0 = fmaxf(mx0, __shfl_xor_sync(0xffffffffu, mx0, 2));
        mx1 = fmaxf(mx1, __shfl_xor_sync(0xffffffffu, mx1, 1));
        mx1 = fmaxf(mx1, __shfl_xor_sync(0xffffffffu, mx1, 2));

        float mn0 = fmaxf(m0, mx0), mn1 = fmaxf(m1, mx1);
        float al0 = __expf(m0 - mn0), al1 = __expf(m1 - mn1);
        m0 = mn0; m1 = mn1;

        float s0 = 0.0f, s1 = 0.0f;
        #pragma unroll
        for (int nt = 0; nt < 16; nt++) {
            float p0 = __expf(accS[nt][0] - mn0);
            float p1 = __expf(accS[nt][1] - mn0);
            float p2 = __expf(accS[nt][2] - mn1);
            float p3 = __expf(accS[nt][3] - mn1);
            accS[nt][0] = p0; accS[nt][1] = p1;
            accS[nt][2] = p2; accS[nt][3] = p3;
            s0 += p0 + p1; s1 += p2 + p3;
        }
        s0 += __shfl_xor_sync(0xffffffffu, s0, 1);
        s0 += __shfl_xor_sync(0xffffffffu, s0, 2);
        s1 += __shfl_xor_sync(0xffffffffu, s1, 1);
        s1 += __shfl_xor_sync(0xffffffffu, s1, 2);
        l0 = l0 * al0 + s0;
        l1 = l1 * al1 + s1;

        #pragma unroll
        for (int i = 0; i < 8; i++) {
            accO[i][0] *= al0; accO[i][1] *= al0;
            accO[i][2] *= al1; accO[i][3] *= al1;
        }

        #pragma unroll
        for (int nt = 0; nt < 16; nt++) {
            uint2 pa, pb;
            pa.x = f2tf32(accS[nt][0]); pa.y = f2tf32(accS[nt][1]);
            pb.x = f2tf32(accS[nt][2]); pb.y = f2tf32(accS[nt][3]);
            *(uint2*)(Ps + (rbase    ) * PSTR + nt * 8 + 2 * tig) = pa;
            *(uint2*)(Ps + (rbase + 8) * PSTR + nt * 8 + 2 * tig) = pb;
        }
        __syncwarp();

        #pragma unroll
        for (int ki = 0; ki < 16; ki++) {
            uint32_t a0 = *(const uint32_t*)(Ps + (rbase    ) * PSTR + ki * 8 + tig);
            uint32_t a1 = *(const uint32_t*)(Ps + (rbase + 8) * PSTR + ki * 8 + tig);
            uint32_t a2 = *(const uint32_t*)(Ps + (rbase    ) * PSTR + ki * 8 + tig + 4);
            uint32_t a3 = *(const uint32_t*)(Ps + (rbase + 8) * PSTR + ki * 8 + tig + 4);
            #pragma unroll
            for (int nt = 0; nt < 8; nt++) {
                uint32_t b0 = *(const uint32_t*)(Vs + (ki * 8 + tig    ) * VSTR + nt * 8 + gid);
                uint32_t b1 = *(const uint32_t*)(Vs + (ki * 8 + tig + 4) * VSTR + nt * 8 + gid);
                asm volatile(
                    "mma.sync.aligned.m16n8k8.row.col.f32.tf32.tf32.f32 "
                    "{%0,%1,%2,%3}, {%4,%5,%6,%7}, {%8,%9}, {%0,%1,%2,%3};\n"
                    : "+f"(accO[nt][0]), "+f"(accO[nt][1]),
                      "+f"(accO[nt][2]), "+f"(accO[nt][3])
                    : "r"(a0), "r"(a1), "r"(a2), "r"(a3), "r"(b0), "r"(b1));
            }
        }
    }

    float inv0 = 1.0f / l0, inv1 = 1.0f / l1;
    #pragma unroll
    for (int nt = 0; nt < 8; nt++) {
        int col = nt * 8 + 2 * tig;
        __half2 o0 = __floats2half2_rn(accO[nt][0] * inv0, accO[nt][1] * inv0);
        __half2 o1 = __floats2half2_rn(accO[nt][2] * inv1, accO[nt][3] * inv1);
        *(__half2*)(O + bout + (size_t)(qt * 128 + rbase    ) * E_DIM + col) = o0;
        *(__half2*)(O + bout + (size_t)(qt * 128 + rbase + 8) * E_DIM + col) = o1;
    }
}

// ---------------------------------------------------------------------------
// Residual add + LayerNorm (writes f32 + half copy)
// ---------------------------------------------------------------------------
__global__ __launch_bounds__(256)
void add_ln_kernel(const float* __restrict__ a, const float* __restrict__ b,
                   const float* __restrict__ g, const float* __restrict__ beta,
                   float* __restrict__ out, __half* __restrict__ outh)
{
    __shared__ float sred[256];
    int row = blockIdx.x;
    int tid = threadIdx.x;
    const float* ar = a + (size_t)row * E_DIM;
    const float* br = b + (size_t)row * E_DIM;
    float* orow = out + (size_t)row * E_DIM;
    __half* ohrow = outh + (size_t)row * E_DIM;

    float xv[4];
    float lsum = 0.0f;
    #pragma unroll
    for (int j = 0; j < 4; j++) {
        int e = tid + j * 256;
        xv[j] = ar[e] + br[e];
        lsum += xv[j];
    }
    sred[tid] = lsum;
    __syncthreads();
    #pragma unroll
    for (int s = 128; s > 0; s >>= 1) {
        if (tid < s) sred[tid] += sred[tid + s];
        __syncthreads();
    }
    float mean = sred[0] * (1.0f / E_DIM);
    __syncthreads();

    float lvar = 0.0f;
    #pragma unroll
    for (int j = 0; j < 4; j++) {
        float d = xv[j] - mean;
        lvar += d * d;
    }
    sred[tid] = lvar;
    __syncthreads();
    #pragma unroll
    for (int s = 128; s > 0; s >>= 1) {
        if (tid < s) sred[tid] += sred[tid + s];
        __syncthreads();
    }
    float rstd = rsqrtf(sred[0] * (1.0f / E_DIM) + 1e-5f);

    #pragma unroll
    for (int j = 0; j < 4; j++) {
        int e = tid + j * 256;
        float v = (xv[j] - mean) * rstd * g[e] + beta[e];
        orow[e] = v;
        ohrow[e] = __float2half_rn(v);
    }
}

// ---------------------------------------------------------------------------
// Launch
// ---------------------------------------------------------------------------
extern "C" void kernel_launch(void* const* d_in, const int* in_sizes, int n_in,
                              void* d_out, int out_size)
{
    const int*   x    = (const int*)  d_in[0];
    const float* emb  = (const float*)d_in[1];
    const float* Wq   = (const float*)d_in[2];
    const float* bq   = (const float*)d_in[3];
    const float* Wk   = (const float*)d_in[4];
    const float* bk   = (const float*)d_in[5];
    const float* Wv   = (const float*)d_in[6];
    const float* bv   = (const float*)d_in[7];
    const float* Wo   = (const float*)d_in[8];
    const float* bo   = (const float*)d_in[9];
    const float* ln1g = (const float*)d_in[10];
    const float* ln1b = (const float*)d_in[11];
    const float* ln2g = (const float*)d_in[12];
    const float* ln2b = (const float*)d_in[13];
    const float* W1   = (const float*)d_in[14];
    const float* b1   = (const float*)d_in[15];
    const float* W2   = (const float*)d_in[16];
    const float* b2   = (const float*)d_in[17];
    const float* Wout = (const float*)d_in[18];
    const float* bout = (const float*)d_in[19];
    float* out = (float*)d_out;

    float *act, *qkv, *tmp, *hbuf, *bqkv;
    __half *act_h, *attn_h, *h_h, *ff_h, *wh;
    cudaGetSymbolAddress((void**)&act,    g_act);
    cudaGetSymbolAddress((void**)&act_h,  g_act_h);
    cudaGetSymbolAddress((void**)&qkv,    g_qkv);
    cudaGetSymbolAddress((void**)&attn_h, g_attn_h);
    cudaGetSymbolAddress((void**)&tmp,    g_tmp);
    cudaGetSymbolAddress((void**)&hbuf,   g_h);
    cudaGetSymbolAddress((void**)&h_h,    g_h_h);
    cudaGetSymbolAddress((void**)&ff_h,   g_ff_h);
    cudaGetSymbolAddress((void**)&bqkv,   g_bqkv);
    cudaGetSymbolAddress((void**)&wh,     g_wh);

    static int attr_set = 0;
    if (!attr_set) {
        cudaFuncSetAttribute(flash_attn,
                             cudaFuncAttributeMaxDynamicSharedMemorySize, ATTN_SMEM);
        cudaFuncSetAttribute(hgemm3<0, 1, 0>,
                             cudaFuncAttributeMaxDynamicSharedMemorySize, GEMM_SMEM);
        cudaFuncSetAttribute(hgemm3<1, 0, 1>,
                             cudaFuncAttributeMaxDynamicSharedMemorySize, GEMM_SMEM);
        attr_set = 1;
    }

    // ---- upfront: weight transposes (batched) + bias pack ----
    {
        dim3 blk(32, 8);
        dim3 gEE(E_DIM / 32, E_DIM / 32, L_NUM);
        transpose_half_b<<<gEE, blk>>>(Wq, wh + 0 * WO_LSTR, E_DIM, E_DIM,
                                       (size_t)E_DIM * E_DIM, QKV_LSTR);
        transpose_half_b<<<gEE, blk>>>(Wk, wh + 1 * WO_LSTR, E_DIM, E_DIM,
                                       (size_t)E_DIM * E_DIM, QKV_LSTR);
        transpose_half_b<<<gEE, blk>>>(Wv, wh + 2 * WO_LSTR, E_DIM, E_DIM,
                                       (size_t)E_DIM * E_DIM, QKV_LSTR);
        transpose_half_b<<<gEE, blk>>>(Wo, wh + OFF_WO, E_DIM, E_DIM,
                                       (size_t)E_DIM * E_DIM, WO_LSTR);
        dim3 gW1(FF_DIM / 32, E_DIM / 32, L_NUM);
        transpose_half_b<<<gW1, blk>>>(W1, wh + OFF_W1, E_DIM, FF_DIM,
                                       (size_t)E_DIM * FF_DIM, W1_LSTR);
        dim3 gW2(E_DIM / 32, FF_DIM / 32, L_NUM);
        transpose_half_b<<<gW2, blk>>>(W2, wh + OFF_W2, FF_DIM, E_DIM,
                                       (size_t)FF_DIM * E_DIM, W2_LSTR);
        dim3 gWV(V_DIM / 32, E_DIM / 32, 1);
        transpose_half_b<<<gWV, blk>>>(Wout, wh + OFF_WOUT, E_DIM, V_DIM,
                                       (size_t)E_DIM * V_DIM, 0);
        pack_qkv_bias<<<(L_NUM * QKV_STR) / 256, 256>>>(bq, bk, bv, bqkv);
    }

    embed_kernel<<<M_TOK, 256>>>(x, emb, act, act_h);

    for (int i = 0; i < L_NUM; i++) {
        size_t bo_off = (size_t)i * E_DIM;

        hgemm3<0, 1, 0><<<dim3(QKV_STR / GBN, M_TOK / GBM), 256, GEMM_SMEM>>>(
            act_h, wh + (size_t)i * QKV_LSTR, bqkv + (size_t)i * QKV_STR,
            qkv, (__half*)0, QKV_STR, E_DIM);

        flash_attn<<<dim3(S_LEN / 128, H_DIM, N_B), 256, ATTN_SMEM>>>(qkv, attn_h);

        hgemm3<0, 1, 0><<<dim3(E_DIM / GBN, M_TOK / GBM), 256, GEMM_SMEM>>>(
            attn_h, wh + OFF_WO + (size_t)i * WO_LSTR, bo + bo_off,
            tmp, (__half*)0, E_DIM, E_DIM);

        add_ln_kernel<<<M_TOK, 256>>>(tmp, act, ln1g + bo_off, ln1b + bo_off,
                                      hbuf, h_h);

        hgemm3<1, 0, 1><<<dim3(FF_DIM / GBN, M_TOK / GBM), 256, GEMM_SMEM>>>(
            h_h, wh + OFF_W1 + (size_t)i * W1_LSTR, b1 + (size_t)i * FF_DIM,
            (float*)0, ff_h, FF_DIM, E_DIM);

        hgemm3<0, 1, 0><<<dim3(E_DIM / GBN, M_TOK / GBM), 256, GEMM_SMEM>>>(
            ff_h, wh + OFF_W2 + (size_t)i * W2_LSTR, b2 + bo_off,
            tmp, (__half*)0, E_DIM, FF_DIM);

        add_ln_kernel<<<M_TOK, 256>>>(tmp, hbuf, ln2g + bo_off, ln2b + bo_off,
                                      act, act_h);
    }

    hgemm3<0, 1, 0><<<dim3(V_DIM / GBN, M_TOK / GBM), 256, GEMM_SMEM>>>(
        act_h, wh + OFF_WOUT, bout, out, (__half*)0, V_DIM, E_DIM);
}

// round 11
// speedup vs baseline: 1.1872x; 1.1872x over previous
#include <cuda_runtime.h>
#include <cuda_fp16.h>
#include <math.h>
#include <stdint.h>

#define E_DIM 1024
#define H_DIM 16
#define D_DIM 64
#define S_LEN 1024
#define N_B   4
#define L_NUM 4
#define FF_DIM 4096
#define V_DIM 32000
#define M_TOK (N_B * S_LEN)   // 4096 token rows
#define QKV_STR (3 * E_DIM)   // 3072

// ---------------------------------------------------------------------------
// Transposed-weight half buffer layout (element offsets)
// ---------------------------------------------------------------------------
#define QKV_LSTR   (3 * E_DIM * E_DIM)
#define OFF_WO     (L_NUM * QKV_LSTR)
#define WO_LSTR    (E_DIM * E_DIM)
#define OFF_W1     (OFF_WO + L_NUM * WO_LSTR)
#define W1_LSTR    (E_DIM * FF_DIM)
#define OFF_W2     (OFF_W1 + L_NUM * W1_LSTR)
#define W2_LSTR    (FF_DIM * E_DIM)
#define OFF_WOUT   (OFF_W2 + L_NUM * W2_LSTR)
#define WH_TOTAL   (OFF_WOUT + (size_t)V_DIM * E_DIM)

// ---------------------------------------------------------------------------
// Scratch (device globals; no allocations allowed)
// ---------------------------------------------------------------------------
__device__ float  g_act  [M_TOK * E_DIM];
__device__ __half g_act_h[M_TOK * E_DIM];
__device__ float  g_qkv  [M_TOK * QKV_STR];
__device__ __half g_attn_h[M_TOK * E_DIM];
__device__ float  g_tmp  [M_TOK * E_DIM];
__device__ float  g_h    [M_TOK * E_DIM];
__device__ __half g_h_h  [M_TOK * E_DIM];
__device__ __half g_ff_h [M_TOK * FF_DIM];
__device__ float  g_bqkv [L_NUM * QKV_STR];
__device__ __half g_wh   [WH_TOTAL];

__device__ __forceinline__ uint32_t f2tf32(float x) {
    uint32_t r;
    asm("cvt.rna.tf32.f32 %0, %1;" : "=r"(r) : "f"(x));
    return r;
}

__device__ __forceinline__ uint32_t smem_u32(const void* p) {
    uint32_t a;
    asm("{ .reg .u64 t; cvta.to.shared.u64 t, %1; cvt.u32.u64 %0, t; }"
        : "=r"(a) : "l"(p));
    return a;
}

__device__ __forceinline__ void ldsm_x4(uint32_t* r, uint32_t addr) {
    asm volatile("ldmatrix.sync.aligned.m8n8.x4.shared.b16 {%0,%1,%2,%3}, [%4];"
                 : "=r"(r[0]), "=r"(r[1]), "=r"(r[2]), "=r"(r[3]) : "r"(addr));
}
__device__ __forceinline__ void ldsm_x2(uint32_t* r, uint32_t addr) {
    asm volatile("ldmatrix.sync.aligned.m8n8.x2.shared.b16 {%0,%1}, [%2];"
                 : "=r"(r[0]), "=r"(r[1]) : "r"(addr));
}

// ---------------------------------------------------------------------------
// Embedding + sinusoidal positional encoding (writes f32 + half copies)
// ---------------------------------------------------------------------------
__global__ void embed_kernel(const int* __restrict__ x,
                             const float* __restrict__ emb,
                             float* __restrict__ out,
                             __half* __restrict__ outh)
{
    int row = blockIdx.x;
    int s   = row & (S_LEN - 1);
    int tok = x[row];
    const float* erow = emb + (size_t)tok * E_DIM;
    float* orow = out + (size_t)row * E_DIM;
    __half* ohrow = outh + (size_t)row * E_DIM;

    int e0 = threadIdx.x * 4;
    #pragma unroll
    for (int j = 0; j < 4; j++) {
        int e = e0 + j;
        int even = e & ~1;
        float expo = (float)even / (float)E_DIM;
        float denom = powf(10000.0f, expo);
        float ang = (float)s / denom;
        float pe = (e & 1) ? cosf(ang) : sinf(ang);
        float v = erow[e] + pe;
        orow[e] = v;
        ohrow[e] = __float2half_rn(v);
    }
}

// ---------------------------------------------------------------------------
// Batched transpose+half: Dz[n][k] = half(Wz[k][n])
// ---------------------------------------------------------------------------
__global__ __launch_bounds__(256)
void transpose_half_b(const float* __restrict__ W, __half* __restrict__ dst,
                      int Kd, int Nd, size_t src_stride, size_t dst_stride)
{
    __shared__ float tile[32][33];
    const float* Wz = W + (size_t)blockIdx.z * src_stride;
    __half* Dz = dst + (size_t)blockIdx.z * dst_stride;
    int n0 = blockIdx.x * 32, k0 = blockIdx.y * 32;
    int tx = threadIdx.x, ty = threadIdx.y;
    #pragma unroll
    for (int dy = 0; dy < 32; dy += 8)
        tile[ty + dy][tx] = Wz[(size_t)(k0 + ty + dy) * Nd + n0 + tx];
    __syncthreads();
    #pragma unroll
    for (int dy = 0; dy < 32; dy += 8)
        Dz[(size_t)(n0 + ty + dy) * Kd + k0 + tx] =
            __float2half_rn(tile[tx][ty + dy]);
}

__global__ void pack_qkv_bias(const float* __restrict__ bq,
                              const float* __restrict__ bk,
                              const float* __restrict__ bv,
                              float* __restrict__ out)
{
    int i = blockIdx.x * 256 + threadIdx.x;
    int layer = i / QKV_STR, c = i % QKV_STR;
    float v;
    if (c < E_DIM)           v = bq[layer * E_DIM + c];
    else if (c < 2 * E_DIM)  v = bk[layer * E_DIM + c - E_DIM];
    else                     v = bv[layer * E_DIM + c - 2 * E_DIM];
    out[i] = v;
}

// ---------------------------------------------------------------------------
// FP16 GEMM, round-7 proven geometry + half-A cp.async + 3-stage pipeline.
// CTA 128x128, warp 64x32, BK=32, ROWB=112 (64B data + pad), 2 CTAs/SM.
// A[M][K] half, Bt[N][K] half row-major, f32 accum.
// ---------------------------------------------------------------------------
#define GBM 128
#define GBN 128
#define GBK 32
#define ROWB 112
#define OP_ST (128 * ROWB)            // 14336 per operand
#define STG   (2 * OP_ST)             // 28672 per stage
#define NST   3
#define GEMM_SMEM (NST * STG)         // 86016

template<int RELU, int WF, int WH>
__global__ __launch_bounds__(256, 2)
void hgemm4(const __half* __restrict__ A, const __half* __restrict__ Bt,
            const float* __restrict__ bias,
            float* __restrict__ Cf, __half* __restrict__ Ch,
            int Nd, int Kd)
{
    extern __shared__ char smem[];
    const uint32_t sbase = smem_u32(smem);

    const int tid  = threadIdx.x;
    const int lane = tid & 31;
    const int wid  = tid >> 5;
    const int gid  = lane >> 2;
    const int tig  = lane & 3;

    const int m0 = blockIdx.y * GBM;
    const int n0 = blockIdx.x * GBN;
    const int wm = (wid >> 2) * 64;
    const int wn = (wid & 3) * 32;

    const int arow = wm + (lane & 15);
    const int akoh = (lane & 16) ? 8 : 0;
    const int brow = wn + (lane & 7);
    const int bkoh = (lane & 8) ? 8 : 0;

    // staging: 4 threads per row, 16B each (64B contiguous per row), 2 passes
    const int s_row = tid >> 2;       // 0..63 (+64 on pass 1)
    const int s_q   = tid & 3;        // 16B chunk

    float acc[4][4][4];
    #pragma unroll
    for (int i = 0; i < 4; i++)
        #pragma unroll
        for (int j = 0; j < 4; j++)
            #pragma unroll
            for (int r = 0; r < 4; r++) acc[i][j][r] = 0.0f;

    const int nK = Kd / GBK;

    auto issue_stage = [&](int t, int buf) {
        const uint32_t base = sbase + buf * STG;
        const __half* Ag = A + (size_t)m0 * Kd + t * GBK;
        const __half* Bg = Bt + (size_t)n0 * Kd + t * GBK;
        #pragma unroll
        for (int p = 0; p < 2; p++) {
            int r = s_row + p * 64;
            uint32_t da = base + r * ROWB + s_q * 16;
            const __half* sa = Ag + (size_t)r * Kd + s_q * 8;
            asm volatile("cp.async.cg.shared.global [%0], [%1], 16;\n"
                         :: "r"(da), "l"(sa));
            uint32_t db = base + OP_ST + r * ROWB + s_q * 16;
            const __half* sb = Bg + (size_t)r * Kd + s_q * 8;
            asm volatile("cp.async.cg.shared.global [%0], [%1], 16;\n"
                         :: "r"(db), "l"(sb));
        }
        asm volatile("cp.async.commit_group;\n");
    };

    // prologue: 2 stages in flight
    issue_stage(0, 0);
    if (nK > 1) issue_stage(1, 1);

    int buf = 0;
    for (int t = 0; t < nK; t++) {
        if (t + 1 < nK) asm volatile("cp.async.wait_group 1;\n");
        else            asm volatile("cp.async.wait_group 0;\n");
        __syncthreads();

        if (t + 2 < nK) {
            int nb = buf + 2; if (nb >= NST) nb -= NST;
            issue_stage(t + 2, nb);
        }

        const uint32_t sA = sbase + buf * STG;
        const uint32_t sB = sA + OP_ST;
        #pragma unroll
        for (int ko = 0; ko < GBK; ko += 16) {
            uint32_t af[4][4], bf[4][2];
            #pragma unroll
            for (int mt = 0; mt < 4; mt++)
                ldsm_x4(af[mt], sA + (arow + mt * 16) * ROWB + (ko + akoh) * 2);
            #pragma unroll
            for (int nt = 0; nt < 4; nt++)
                ldsm_x2(bf[nt], sB + (brow + nt * 8) * ROWB + (ko + bkoh) * 2);
            #pragma unroll
            for (int mt = 0; mt < 4; mt++)
                #pragma unroll
                for (int nt = 0; nt < 4; nt++) {
                    asm volatile(
                        "mma.sync.aligned.m16n8k16.row.col.f32.f16.f16.f32 "
                        "{%0,%1,%2,%3}, {%4,%5,%6,%7}, {%8,%9}, {%0,%1,%2,%3};\n"
                        : "+f"(acc[mt][nt][0]), "+f"(acc[mt][nt][1]),
                          "+f"(acc[mt][nt][2]), "+f"(acc[mt][nt][3])
                        : "r"(af[mt][0]), "r"(af[mt][1]),
                          "r"(af[mt][2]), "r"(af[mt][3]),
                          "r"(bf[nt][0]), "r"(bf[nt][1]));
                }
        }
        if (++buf >= NST) buf = 0;
    }

    // epilogue
    #pragma unroll
    for (int nt = 0; nt < 4; nt++) {
        int col = n0 + wn + nt * 8 + 2 * tig;
        float b0 = bias[col];
        float b1 = bias[col + 1];
        #pragma unroll
        for (int mt = 0; mt < 4; mt++) {
            int row = m0 + wm + mt * 16 + gid;
            float v00 = acc[mt][nt][0] + b0;
            float v01 = acc[mt][nt][1] + b1;
            float v10 = acc[mt][nt][2] + b0;
            float v11 = acc[mt][nt][3] + b1;
            if (RELU) {
                v00 = fmaxf(v00, 0.0f); v01 = fmaxf(v01, 0.0f);
                v10 = fmaxf(v10, 0.0f); v11 = fmaxf(v11, 0.0f);
            }
            if (WF) {
                float2 f0 = {v00, v01}, f1 = {v10, v11};
                *(float2*)(Cf + (size_t)row * Nd + col)       = f0;
                *(float2*)(Cf + (size_t)(row + 8) * Nd + col) = f1;
            }
            if (WH) {
                __half2 h0 = __floats2half2_rn(v00, v01);
                __half2 h1 = __floats2half2_rn(v10, v11);
                *(__half2*)(Ch + (size_t)row * Nd + col)       = h0;
                *(__half2*)(Ch + (size_t)(row + 8) * Nd + col) = h1;
            }
        }
    }
}

// ---------------------------------------------------------------------------
// Flash attention (tf32 mma.sync); reads fused QKV f32, writes half O.
// ---------------------------------------------------------------------------
#define QSTR 68
#define KSTR 68
#define VSTR 72
#define PSTR 132
#define ATTN_SMEM ((128*QSTR + 128*KSTR + 128*VSTR + 128*PSTR) * 4)

__global__ __launch_bounds__(256)
void flash_attn(const float* __restrict__ QKV, __half* __restrict__ O)
{
    extern __shared__ float sm[];
    float* Qs = sm;
    float* Ks = Qs + 128 * QSTR;
    float* Vs = Ks + 128 * KSTR;
    float* Ps = Vs + 128 * VSTR;

    const int tid  = threadIdx.x;
    const int lane = tid & 31;
    const int wid  = tid >> 5;
    const int gid  = lane >> 2;
    const int tig  = lane & 3;

    const int qt = gridDim.x - 1 - blockIdx.x;
    const int h  = blockIdx.y;
    const int n  = blockIdx.z;
    const size_t binq = ((size_t)n * S_LEN) * QKV_STR + h * D_DIM;
    const size_t bink = binq + E_DIM;
    const size_t binv = binq + 2 * E_DIM;
    const size_t bout = ((size_t)n * S_LEN) * E_DIM + h * D_DIM;
    const float scale = 1.0f / 32.0f;
    const int wrow = wid * 16;

    #pragma unroll
    for (int l = 0; l < 8; l++) {
        int idx = tid + l * 256;
        int r = idx >> 4, c4 = (idx & 15) * 4;
        float4 v = *(const float4*)(QKV + binq + (size_t)(qt * 128 + r) * QKV_STR + c4);
        uint4 u;
        u.x = f2tf32(v.x * scale); u.y = f2tf32(v.y * scale);
        u.z = f2tf32(v.z * scale); u.w = f2tf32(v.w * scale);
        *(uint4*)(Qs + r * QSTR + c4) = u;
    }

    float accO[8][4];
    #pragma unroll
    for (int i = 0; i < 8; i++)
        #pragma unroll
        for (int j = 0; j < 4; j++) accO[i][j] = 0.0f;
    float m0 = -1e30f, m1 = -1e30f, l0 = 0.0f, l1 = 0.0f;

    const int rbase = wrow + gid;

    for (int kt = 0; kt <= qt; kt++) {
        __syncthreads();
        #pragma unroll
        for (int l = 0; l < 8; l++) {
            int idx = tid + l * 256;
            int r = idx >> 4, c4 = (idx & 15) * 4;
            const size_t roff = (size_t)(kt * 128 + r) * QKV_STR + c4;
            float4 kv = *(const float4*)(QKV + bink + roff);
            uint4 ku;
            ku.x = f2tf32(kv.x); ku.y = f2tf32(kv.y);
            ku.z = f2tf32(kv.z); ku.w = f2tf32(kv.w);
            *(uint4*)(Ks + r * KSTR + c4) = ku;
            float4 vv = *(const float4*)(QKV + binv + roff);
            uint4 vu;
            vu.x = f2tf32(vv.x); vu.y = f2tf32(vv.y);
            vu.z = f2tf32(vv.z); vu.w = f2tf32(vv.w);
            *(uint4*)(Vs + r * VSTR + c4) = vu;
        }
        __syncthreads();

        float accS[16][4];
        #pragma unroll
        for (int i = 0; i < 16; i++)
            #pragma unroll
            for (int j = 0; j < 4; j++) accS[i][j] = 0.0f;

        #pragma unroll
        for (int ks = 0; ks < 8; ks++) {
            uint32_t a0 = *(const uint32_t*)(Qs + (rbase    ) * QSTR + ks * 8 + tig);
            uint32_t a1 = *(const uint32_t*)(Qs + (rbase + 8) * QSTR + ks * 8 + tig);
            uint32_t a2 = *(const uint32_t*)(Qs + (rbase    ) * QSTR + ks * 8 + tig + 4);
            uint32_t a3 = *(const uint32_t*)(Qs + (rbase + 8) * QSTR + ks * 8 + tig + 4);
            #pragma unroll
            for (int nt = 0; nt < 16; nt++) {
                uint32_t b0 = *(const uint32_t*)(Ks + (nt * 8 + gid) * KSTR + ks * 8 + tig);
                uint32_t b1 = *(const uint32_t*)(Ks + (nt * 8 + gid) * KSTR + ks * 8 + tig + 4);
                asm volatile(
                    "mma.sync.aligned.m16n8k8.row.col.f32.tf32.tf32.f32 "
                    "{%0,%1,%2,%3}, {%4,%5,%6,%7}, {%8,%9}, {%0,%1,%2,%3};\n"
                    : "+f"(accS[nt][0]), "+f"(accS[nt][1]),
                      "+f"(accS[nt][2]), "+f"(accS[nt][3])
                    : "r"(a0), "r"(a1), "r"(a2), "r"(a3), "r"(b0), "r"(b1));
            }
        }

        if (kt == qt) {
            #pragma unroll
            for (int nt = 0; nt < 16; nt++) {
                int c = nt * 8 + 2 * tig;
                if (c     > rbase    ) accS[nt][0] = -1e30f;
                if (c + 1 > rbase    ) accS[nt][1] = -1e30f;
                if (c     > rbase + 8) accS[nt][2] = -1e30f;
                if (c + 1 > rbase + 8) accS[nt][3] = -1e30f;
            }
        }

        float mx0 = -1e30f, mx1 = -1e30f;
        #pragma unroll
        for (int nt = 0; nt < 16; nt++) {
            mx0 = fmaxf(mx0, fmaxf(accS[nt][0], accS[nt][1]));
            mx1 = fmaxf(mx1, fmaxf(accS[nt][2], accS[nt][3]));
        }
        mx0 = fmaxf(mx0, __shfl_xor_sync(0xffffffffu, mx0, 1));
        mx0 = fmaxf(mx0, __shfl_xor_sync(0xffffffffu, mx0, 2));
        mx1 = fmaxf(mx1, __shfl_xor_sync(0xffffffffu, mx1, 1));
        mx1 = fmaxf(mx1, __shfl_xor_sync(0xffffffffu, mx1, 2));

        float mn0 = fmaxf(m0, mx0), mn1 = fmaxf(m1, mx1);
        float al0 = __expf(m0 - mn0), al1 = __expf(m1 - mn1);
        m0 = mn0; m1 = mn1;

        float s0 = 0.0f, s1 = 0.0f;
        #pragma unroll
        for (int nt = 0; nt < 16; nt++) {
            float p0 = __expf(accS[nt][0] - mn0);
            float p1 = __expf(accS[nt][1] - mn0);
            float p2 = __expf(accS[nt][2] - mn1);
            float p3 = __expf(accS[nt][3] - mn1);
            accS[nt][0] = p0; accS[nt][1] = p1;
            accS[nt][2] = p2; accS[nt][3] = p3;
            s0 += p0 + p1; s1 += p2 + p3;
        }
        s0 += __shfl_xor_sync(0xffffffffu, s0, 1);
        s0 += __shfl_xor_sync(0xffffffffu, s0, 2);
        s1 += __shfl_xor_sync(0xffffffffu, s1, 1);
        s1 += __shfl_xor_sync(0xffffffffu, s1, 2);
        l0 = l0 * al0 + s0;
        l1 = l1 * al1 + s1;

        #pragma unroll
        for (int i = 0; i < 8; i++) {
            accO[i][0] *= al0; accO[i][1] *= al0;
            accO[i][2] *= al1; accO[i][3] *= al1;
        }

        #pragma unroll
        for (int nt = 0; nt < 16; nt++) {
            uint2 pa, pb;
            pa.x = f2tf32(accS[nt][0]); pa.y = f2tf32(accS[nt][1]);
            pb.x = f2tf32(accS[nt][2]); pb.y = f2tf32(accS[nt][3]);
            *(uint2*)(Ps + (rbase    ) * PSTR + nt * 8 + 2 * tig) = pa;
            *(uint2*)(Ps + (rbase + 8) * PSTR + nt * 8 + 2 * tig) = pb;
        }
        __syncwarp();

        #pragma unroll
        for (int ki = 0; ki < 16; ki++) {
            uint32_t a0 = *(const uint32_t*)(Ps + (rbase    ) * PSTR + ki * 8 + tig);
            uint32_t a1 = *(const uint32_t*)(Ps + (rbase + 8) * PSTR + ki * 8 + tig);
            uint32_t a2 = *(const uint32_t*)(Ps + (rbase    ) * PSTR + ki * 8 + tig + 4);
            uint32_t a3 = *(const uint32_t*)(Ps + (rbase + 8) * PSTR + ki * 8 + tig + 4);
            #pragma unroll
            for (int nt = 0; nt < 8; nt++) {
                uint32_t b0 = *(const uint32_t*)(Vs + (ki * 8 + tig    ) * VSTR + nt * 8 + gid);
                uint32_t b1 = *(const uint32_t*)(Vs + (ki * 8 + tig + 4) * VSTR + nt * 8 + gid);
                asm volatile(
                    "mma.sync.aligned.m16n8k8.row.col.f32.tf32.tf32.f32 "
                    "{%0,%1,%2,%3}, {%4,%5,%6,%7}, {%8,%9}, {%0,%1,%2,%3};\n"
                    : "+f"(accO[nt][0]), "+f"(accO[nt][1]),
                      "+f"(accO[nt][2]), "+f"(accO[nt][3])
                    : "r"(a0), "r"(a1), "r"(a2), "r"(a3), "r"(b0), "r"(b1));
            }
        }
    }

    float inv0 = 1.0f / l0, inv1 = 1.0f / l1;
    #pragma unroll
    for (int nt = 0; nt < 8; nt++) {
        int col = nt * 8 + 2 * tig;
        __half2 o0 = __floats2half2_rn(accO[nt][0] * inv0, accO[nt][1] * inv0);
        __half2 o1 = __floats2half2_rn(accO[nt][2] * inv1, accO[nt][3] * inv1);
        *(__half2*)(O + bout + (size_t)(qt * 128 + rbase    ) * E_DIM + col) = o0;
        *(__half2*)(O + bout + (size_t)(qt * 128 + rbase + 8) * E_DIM + col) = o1;
    }
}

// ---------------------------------------------------------------------------
// Residual add + LayerNorm (writes f32 + half copy)
// ---------------------------------------------------------------------------
__global__ __launch_bounds__(256)
void add_ln_kernel(const float* __restrict__ a, const float* __restrict__ b,
                   const float* __restrict__ g, const float* __restrict__ beta,
                   float* __restrict__ out, __half* __restrict__ outh)
{
    __shared__ float sred[256];
    int row = blockIdx.x;
    int tid = threadIdx.x;
    const float* ar = a + (size_t)row * E_DIM;
    const float* br = b + (size_t)row * E_DIM;
    float* orow = out + (size_t)row * E_DIM;
    __half* ohrow = outh + (size_t)row * E_DIM;

    float xv[4];
    float lsum = 0.0f;
    #pragma unroll
    for (int j = 0; j < 4; j++) {
        int e = tid + j * 256;
        xv[j] = ar[e] + br[e];
        lsum += xv[j];
    }
    sred[tid] = lsum;
    __syncthreads();
    #pragma unroll
    for (int s = 128; s > 0; s >>= 1) {
        if (tid < s) sred[tid] += sred[tid + s];
        __syncthreads();
    }
    float mean = sred[0] * (1.0f / E_DIM);
    __syncthreads();

    float lvar = 0.0f;
    #pragma unroll
    for (int j = 0; j < 4; j++) {
        float d = xv[j] - mean;
        lvar += d * d;
    }
    sred[tid] = lvar;
    __syncthreads();
    #pragma unroll
    for (int s = 128; s > 0; s >>= 1) {
        if (tid < s) sred[tid] += sred[tid + s];
        __syncthreads();
    }
    float rstd = rsqrtf(sred[0] * (1.0f / E_DIM) + 1e-5f);

    #pragma unroll
    for (int j = 0; j < 4; j++) {
        int e = tid + j * 256;
        float v = (xv[j] - mean) * rstd * g[e] + beta[e];
        orow[e] = v;
        ohrow[e] = __float2half_rn(v);
    }
}

// ---------------------------------------------------------------------------
// Launch
// ---------------------------------------------------------------------------
extern "C" void kernel_launch(void* const* d_in, const int* in_sizes, int n_in,
                              void* d_out, int out_size)
{
    const int*   x    = (const int*)  d_in[0];
    const float* emb  = (const float*)d_in[1];
    const float* Wq   = (const float*)d_in[2];
    const float* bq   = (const float*)d_in[3];
    const float* Wk   = (const float*)d_in[4];
    const float* bk   = (const float*)d_in[5];
    const float* Wv   = (const float*)d_in[6];
    const float* bv   = (const float*)d_in[7];
    const float* Wo   = (const float*)d_in[8];
    const float* bo   = (const float*)d_in[9];
    const float* ln1g = (const float*)d_in[10];
    const float* ln1b = (const float*)d_in[11];
    const float* ln2g = (const float*)d_in[12];
    const float* ln2b = (const float*)d_in[13];
    const float* W1   = (const float*)d_in[14];
    const float* b1   = (const float*)d_in[15];
    const float* W2   = (const float*)d_in[16];
    const float* b2   = (const float*)d_in[17];
    const float* Wout = (const float*)d_in[18];
    const float* bout = (const float*)d_in[19];
    float* out = (float*)d_out;

    float *act, *qkv, *tmp, *hbuf, *bqkv;
    __half *act_h, *attn_h, *h_h, *ff_h, *wh;
    cudaGetSymbolAddress((void**)&act,    g_act);
    cudaGetSymbolAddress((void**)&act_h,  g_act_h);
    cudaGetSymbolAddress((void**)&qkv,    g_qkv);
    cudaGetSymbolAddress((void**)&attn_h, g_attn_h);
    cudaGetSymbolAddress((void**)&tmp,    g_tmp);
    cudaGetSymbolAddress((void**)&hbuf,   g_h);
    cudaGetSymbolAddress((void**)&h_h,    g_h_h);
    cudaGetSymbolAddress((void**)&ff_h,   g_ff_h);
    cudaGetSymbolAddress((void**)&bqkv,   g_bqkv);
    cudaGetSymbolAddress((void**)&wh,     g_wh);

    static int attr_set = 0;
    if (!attr_set) {
        cudaFuncSetAttribute(flash_attn,
                             cudaFuncAttributeMaxDynamicSharedMemorySize, ATTN_SMEM);
        cudaFuncSetAttribute(hgemm4<0, 1, 0>,
                             cudaFuncAttributeMaxDynamicSharedMemorySize, GEMM_SMEM);
        cudaFuncSetAttribute(hgemm4<1, 0, 1>,
                             cudaFuncAttributeMaxDynamicSharedMemorySize, GEMM_SMEM);
        attr_set = 1;
    }

    // ---- upfront: weight transposes (batched) + bias pack ----
    {
        dim3 blk(32, 8);
        dim3 gEE(E_DIM / 32, E_DIM / 32, L_NUM);
        transpose_half_b<<<gEE, blk>>>(Wq, wh + 0 * WO_LSTR, E_DIM, E_DIM,
                                       (size_t)E_DIM * E_DIM, QKV_LSTR);
        transpose_half_b<<<gEE, blk>>>(Wk, wh + 1 * WO_LSTR, E_DIM, E_DIM,
                                       (size_t)E_DIM * E_DIM, QKV_LSTR);
        transpose_half_b<<<gEE, blk>>>(Wv, wh + 2 * WO_LSTR, E_DIM, E_DIM,
                                       (size_t)E_DIM * E_DIM, QKV_LSTR);
        transpose_half_b<<<gEE, blk>>>(Wo, wh + OFF_WO, E_DIM, E_DIM,
                                       (size_t)E_DIM * E_DIM, WO_LSTR);
        dim3 gW1(FF_DIM / 32, E_DIM / 32, L_NUM);
        transpose_half_b<<<gW1, blk>>>(W1, wh + OFF_W1, E_DIM, FF_DIM,
                                       (size_t)E_DIM * FF_DIM, W1_LSTR);
        dim3 gW2(E_DIM / 32, FF_DIM / 32, L_NUM);
        transpose_half_b<<<gW2, blk>>>(W2, wh + OFF_W2, FF_DIM, E_DIM,
                                       (size_t)FF_DIM * E_DIM, W2_LSTR);
        dim3 gWV(V_DIM / 32, E_DIM / 32, 1);
        transpose_half_b<<<gWV, blk>>>(Wout, wh + OFF_WOUT, E_DIM, V_DIM,
                                       (size_t)E_DIM * V_DIM, 0);
        pack_qkv_bias<<<(L_NUM * QKV_STR) / 256, 256>>>(bq, bk, bv, bqkv);
    }

    embed_kernel<<<M_TOK, 256>>>(x, emb, act, act_h);

    for (int i = 0; i < L_NUM; i++) {
        size_t bo_off = (size_t)i * E_DIM;

        hgemm4<0, 1, 0><<<dim3(QKV_STR / GBN, M_TOK / GBM), 256, GEMM_SMEM>>>(
            act_h, wh + (size_t)i * QKV_LSTR, bqkv + (size_t)i * QKV_STR,
            qkv, (__half*)0, QKV_STR, E_DIM);

        flash_attn<<<dim3(S_LEN / 128, H_DIM, N_B), 256, ATTN_SMEM>>>(qkv, attn_h);

        hgemm4<0, 1, 0><<<dim3(E_DIM / GBN, M_TOK / GBM), 256, GEMM_SMEM>>>(
            attn_h, wh + OFF_WO + (size_t)i * WO_LSTR, bo + bo_off,
            tmp, (__half*)0, E_DIM, E_DIM);

        add_ln_kernel<<<M_TOK, 256>>>(tmp, act, ln1g + bo_off, ln1b + bo_off,
                                      hbuf, h_h);

        hgemm4<1, 0, 1><<<dim3(FF_DIM / GBN, M_TOK / GBM), 256, GEMM_SMEM>>>(
            h_h, wh + OFF_W1 + (size_t)i * W1_LSTR, b1 + (size_t)i * FF_DIM,
            (float*)0, ff_h, FF_DIM, E_DIM);

        hgemm4<0, 1, 0><<<dim3(E_DIM / GBN, M_TOK / GBM), 256, GEMM_SMEM>>>(
            ff_h, wh + OFF_W2 + (size_t)i * W2_LSTR, b2 + bo_off,
            tmp, (__half*)0, E_DIM, FF_DIM);

        add_ln_kernel<<<M_TOK, 256>>>(tmp, hbuf, ln2g + bo_off, ln2b + bo_off,
                                      act, act_h);
    }

    hgemm4<0, 1, 0><<<dim3(V_DIM / GBN, M_TOK / GBM), 256, GEMM_SMEM>>>(
        act_h, wh + OFF_WOUT, bout, out, (__half*)0, V_DIM, E_DIM);
}

// round 12
// speedup vs baseline: 1.2742x; 1.0732x over previous
#include <cuda_runtime.h>
#include <cuda_fp16.h>
#include <math.h>
#include <stdint.h>

#define E_DIM 1024
#define H_DIM 16
#define D_DIM 64
#define S_LEN 1024
#define N_B   4
#define L_NUM 4
#define FF_DIM 4096
#define V_DIM 32000
#define M_TOK (N_B * S_LEN)   // 4096 token rows
#define QKV_STR (3 * E_DIM)   // 3072

// ---------------------------------------------------------------------------
// Transposed-weight half buffer layout (element offsets)
// ---------------------------------------------------------------------------
#define QKV_LSTR   (3 * E_DIM * E_DIM)
#define OFF_WO     (L_NUM * QKV_LSTR)
#define WO_LSTR    (E_DIM * E_DIM)
#define OFF_W1     (OFF_WO + L_NUM * WO_LSTR)
#define W1_LSTR    (E_DIM * FF_DIM)
#define OFF_W2     (OFF_W1 + L_NUM * W1_LSTR)
#define W2_LSTR    (FF_DIM * E_DIM)
#define OFF_WOUT   (OFF_W2 + L_NUM * W2_LSTR)
#define WH_TOTAL   (OFF_WOUT + (size_t)V_DIM * E_DIM)

// ---------------------------------------------------------------------------
// Scratch (device globals; no allocations allowed)
// ---------------------------------------------------------------------------
__device__ float  g_act  [M_TOK * E_DIM];
__device__ __half g_act_h[M_TOK * E_DIM];
__device__ __half g_qkv_h[M_TOK * QKV_STR];
__device__ __half g_attn_h[M_TOK * E_DIM];
__device__ float  g_tmp  [M_TOK * E_DIM];
__device__ float  g_h    [M_TOK * E_DIM];
__device__ __half g_h_h  [M_TOK * E_DIM];
__device__ __half g_ff_h [M_TOK * FF_DIM];
__device__ float  g_bqkv [L_NUM * QKV_STR];
__device__ __half g_wh   [WH_TOTAL];

__device__ __forceinline__ uint32_t smem_u32(const void* p) {
    uint32_t a;
    asm("{ .reg .u64 t; cvta.to.shared.u64 t, %1; cvt.u32.u64 %0, t; }"
        : "=r"(a) : "l"(p));
    return a;
}

__device__ __forceinline__ void ldsm_x4(uint32_t* r, uint32_t addr) {
    asm volatile("ldmatrix.sync.aligned.m8n8.x4.shared.b16 {%0,%1,%2,%3}, [%4];"
                 : "=r"(r[0]), "=r"(r[1]), "=r"(r[2]), "=r"(r[3]) : "r"(addr));
}
__device__ __forceinline__ void ldsm_x2(uint32_t* r, uint32_t addr) {
    asm volatile("ldmatrix.sync.aligned.m8n8.x2.shared.b16 {%0,%1}, [%2];"
                 : "=r"(r[0]), "=r"(r[1]) : "r"(addr));
}
__device__ __forceinline__ void ldsm_x4t(uint32_t* r, uint32_t addr) {
    asm volatile("ldmatrix.sync.aligned.m8n8.x4.trans.shared.b16 {%0,%1,%2,%3}, [%4];"
                 : "=r"(r[0]), "=r"(r[1]), "=r"(r[2]), "=r"(r[3]) : "r"(addr));
}
__device__ __forceinline__ void mma16816(float* c, const uint32_t* a,
                                         uint32_t b0, uint32_t b1) {
    asm volatile(
        "mma.sync.aligned.m16n8k16.row.col.f32.f16.f16.f32 "
        "{%0,%1,%2,%3}, {%4,%5,%6,%7}, {%8,%9}, {%0,%1,%2,%3};\n"
        : "+f"(c[0]), "+f"(c[1]), "+f"(c[2]), "+f"(c[3])
        : "r"(a[0]), "r"(a[1]), "r"(a[2]), "r"(a[3]), "r"(b0), "r"(b1));
}
__device__ __forceinline__ uint32_t f22h(float a, float b) {
    __half2 h = __floats2half2_rn(a, b);
    return *(uint32_t*)&h;
}

// ---------------------------------------------------------------------------
// Embedding + sinusoidal positional encoding (writes f32 + half copies)
// ---------------------------------------------------------------------------
__global__ void embed_kernel(const int* __restrict__ x,
                             const float* __restrict__ emb,
                             float* __restrict__ out,
                             __half* __restrict__ outh)
{
    int row = blockIdx.x;
    int s   = row & (S_LEN - 1);
    int tok = x[row];
    const float* erow = emb + (size_t)tok * E_DIM;
    float* orow = out + (size_t)row * E_DIM;
    __half* ohrow = outh + (size_t)row * E_DIM;

    int e0 = threadIdx.x * 4;
    #pragma unroll
    for (int j = 0; j < 4; j++) {
        int e = e0 + j;
        int even = e & ~1;
        float expo = (float)even / (float)E_DIM;
        float denom = powf(10000.0f, expo);
        float ang = (float)s / denom;
        float pe = (e & 1) ? cosf(ang) : sinf(ang);
        float v = erow[e] + pe;
        orow[e] = v;
        ohrow[e] = __float2half_rn(v);
    }
}

// ---------------------------------------------------------------------------
// Batched transpose+half, vectorized stores: Dz[n][k] = half(Wz[k][n])
// block (32,8); tile 64k x 32n; grid (N/32, K/64, L)
// ---------------------------------------------------------------------------
__global__ __launch_bounds__(256)
void transpose_half_b2(const float* __restrict__ W, __half* __restrict__ dst,
                       int Kd, int Nd, size_t src_stride, size_t dst_stride)
{
    __shared__ float tile[64][33];
    const float* Wz = W + (size_t)blockIdx.z * src_stride;
    __half* Dz = dst + (size_t)blockIdx.z * dst_stride;
    int n0 = blockIdx.x * 32, k0 = blockIdx.y * 64;
    int tx = threadIdx.x, ty = threadIdx.y;
    #pragma unroll
    for (int i = 0; i < 8; i++)
        tile[ty + 8 * i][tx] = Wz[(size_t)(k0 + ty + 8 * i) * Nd + n0 + tx];
    __syncthreads();
    #pragma unroll
    for (int i = 0; i < 4; i++) {
        int nr = ty + 8 * i;
        __half2 v = __floats2half2_rn(tile[2 * tx][nr], tile[2 * tx + 1][nr]);
        *(__half2*)(Dz + (size_t)(n0 + nr) * Kd + k0 + 2 * tx) = v;
    }
}

__global__ void pack_qkv_bias(const float* __restrict__ bq,
                              const float* __restrict__ bk,
                              const float* __restrict__ bv,
                              float* __restrict__ out)
{
    int i = blockIdx.x * 256 + threadIdx.x;
    int layer = i / QKV_STR, c = i % QKV_STR;
    float v;
    if (c < E_DIM)           v = bq[layer * E_DIM + c];
    else if (c < 2 * E_DIM)  v = bk[layer * E_DIM + c - E_DIM];
    else                     v = bv[layer * E_DIM + c - 2 * E_DIM];
    out[i] = v;
}

// ---------------------------------------------------------------------------
// FP16 GEMM (round-11 core): CTA 128x128, warp 64x32, BK=32, ROWB=112,
// 3-stage cp.async, 2 CTAs/SM. A[M][K] half, Bt[N][K] half, f32 accum.
// ---------------------------------------------------------------------------
#define GBM 128
#define GBN 128
#define GBK 32
#define ROWB 112
#define OP_ST (128 * ROWB)
#define STG   (2 * OP_ST)
#define NST   3
#define GEMM_SMEM (NST * STG)

template<int RELU, int WF, int WH>
__global__ __launch_bounds__(256, 2)
void hgemm4(const __half* __restrict__ A, const __half* __restrict__ Bt,
            const float* __restrict__ bias,
            float* __restrict__ Cf, __half* __restrict__ Ch,
            int Nd, int Kd)
{
    extern __shared__ char smem[];
    const uint32_t sbase = smem_u32(smem);

    const int tid  = threadIdx.x;
    const int lane = tid & 31;
    const int wid  = tid >> 5;
    const int gid  = lane >> 2;
    const int tig  = lane & 3;

    const int m0 = blockIdx.y * GBM;
    const int n0 = blockIdx.x * GBN;
    const int wm = (wid >> 2) * 64;
    const int wn = (wid & 3) * 32;

    const int arow = wm + (lane & 15);
    const int akoh = (lane & 16) ? 8 : 0;
    const int brow = wn + (lane & 7);
    const int bkoh = (lane & 8) ? 8 : 0;

    const int s_row = tid >> 2;
    const int s_q   = tid & 3;

    float acc[4][4][4];
    #pragma unroll
    for (int i = 0; i < 4; i++)
        #pragma unroll
        for (int j = 0; j < 4; j++)
            #pragma unroll
            for (int r = 0; r < 4; r++) acc[i][j][r] = 0.0f;

    const int nK = Kd / GBK;

    auto issue_stage = [&](int t, int buf) {
        const uint32_t base = sbase + buf * STG;
        const __half* Ag = A + (size_t)m0 * Kd + t * GBK;
        const __half* Bg = Bt + (size_t)n0 * Kd + t * GBK;
        #pragma unroll
        for (int p = 0; p < 2; p++) {
            int r = s_row + p * 64;
            uint32_t da = base + r * ROWB + s_q * 16;
            const __half* sa = Ag + (size_t)r * Kd + s_q * 8;
            asm volatile("cp.async.cg.shared.global [%0], [%1], 16;\n"
                         :: "r"(da), "l"(sa));
            uint32_t db = base + OP_ST + r * ROWB + s_q * 16;
            const __half* sb = Bg + (size_t)r * Kd + s_q * 8;
            asm volatile("cp.async.cg.shared.global [%0], [%1], 16;\n"
                         :: "r"(db), "l"(sb));
        }
        asm volatile("cp.async.commit_group;\n");
    };

    issue_stage(0, 0);
    if (nK > 1) issue_stage(1, 1);

    int buf = 0;
    for (int t = 0; t < nK; t++) {
        if (t + 1 < nK) asm volatile("cp.async.wait_group 1;\n");
        else            asm volatile("cp.async.wait_group 0;\n");
        __syncthreads();

        if (t + 2 < nK) {
            int nb = buf + 2; if (nb >= NST) nb -= NST;
            issue_stage(t + 2, nb);
        }

        const uint32_t sA = sbase + buf * STG;
        const uint32_t sB = sA + OP_ST;
        #pragma unroll
        for (int ko = 0; ko < GBK; ko += 16) {
            uint32_t af[4][4], bf[4][2];
            #pragma unroll
            for (int mt = 0; mt < 4; mt++)
                ldsm_x4(af[mt], sA + (arow + mt * 16) * ROWB + (ko + akoh) * 2);
            #pragma unroll
            for (int nt = 0; nt < 4; nt++)
                ldsm_x2(bf[nt], sB + (brow + nt * 8) * ROWB + (ko + bkoh) * 2);
            #pragma unroll
            for (int mt = 0; mt < 4; mt++)
                #pragma unroll
                for (int nt = 0; nt < 4; nt++)
                    mma16816(acc[mt][nt], af[mt], bf[nt][0], bf[nt][1]);
        }
        if (++buf >= NST) buf = 0;
    }

    #pragma unroll
    for (int nt = 0; nt < 4; nt++) {
        int col = n0 + wn + nt * 8 + 2 * tig;
        float b0 = bias[col];
        float b1 = bias[col + 1];
        #pragma unroll
        for (int mt = 0; mt < 4; mt++) {
            int row = m0 + wm + mt * 16 + gid;
            float v00 = acc[mt][nt][0] + b0;
            float v01 = acc[mt][nt][1] + b1;
            float v10 = acc[mt][nt][2] + b0;
            float v11 = acc[mt][nt][3] + b1;
            if (RELU) {
                v00 = fmaxf(v00, 0.0f); v01 = fmaxf(v01, 0.0f);
                v10 = fmaxf(v10, 0.0f); v11 = fmaxf(v11, 0.0f);
            }
            if (WF) {
                float2 f0 = {v00, v01}, f1 = {v10, v11};
                *(float2*)(Cf + (size_t)row * Nd + col)       = f0;
                *(float2*)(Cf + (size_t)(row + 8) * Nd + col) = f1;
            }
            if (WH) {
                __half2 h0 = __floats2half2_rn(v00, v01);
                __half2 h1 = __floats2half2_rn(v10, v11);
                *(__half2*)(Ch + (size_t)row * Nd + col)       = h0;
                *(__half2*)(Ch + (size_t)(row + 8) * Nd + col) = h1;
            }
        }
    }
}

// ---------------------------------------------------------------------------
// FP16 flash attention. One CTA (8 warps) per (n, h, 128-q tile).
// Q/K/V staged half via cp.async from fused qkv_h [row][3072].
// S and PV via mma.m16n8k16.f16; P kept in registers (accS layout == A frag).
// V B-fragments via ldmatrix.x4.trans. K/V double-buffered.
// ---------------------------------------------------------------------------
#define AROWB 144                 // 128B data + 16B pad per smem row
#define AOP   (128 * AROWB)       // 18432
#define ATTN_SMEM (5 * AOP)       // Q + 2K + 2V = 92160

__global__ __launch_bounds__(256)
void flash_attn_h(const __half* __restrict__ QKV, __half* __restrict__ O)
{
    extern __shared__ char smem[];
    const uint32_t sbase = smem_u32(smem);
    const uint32_t sQ = sbase;

    const int tid  = threadIdx.x;
    const int lane = tid & 31;
    const int wid  = tid >> 5;
    const int gid  = lane >> 2;
    const int tig  = lane & 3;

    const int qt = gridDim.x - 1 - blockIdx.x;   // big tiles first
    const int h  = blockIdx.y;
    const int n  = blockIdx.z;
    const size_t rowbase = (size_t)n * S_LEN;
    const int hq = h * D_DIM;
    const int hk = E_DIM + h * D_DIM;
    const int hv = 2 * E_DIM + h * D_DIM;
    const size_t bout = rowbase * E_DIM + h * D_DIM;
    const float scale = 1.0f / 32.0f;
    const int wrow = wid * 16;
    const int rbase = wrow + gid;

    const int s_r = tid >> 2;       // 0..63 (+64)
    const int s_q = tid & 3;        // chunk pairs

    // ---- stage Q (tile qt) ----
    #pragma unroll
    for (int p = 0; p < 2; p++) {
        int r = s_r + p * 64;
        const __half* src = QKV + (rowbase + qt * 128 + r) * QKV_STR + hq;
        #pragma unroll
        for (int j = 0; j < 2; j++) {
            int q = s_q + j * 4;
            asm volatile("cp.async.cg.shared.global [%0], [%1], 16;\n"
                         :: "r"(sQ + r * AROWB + q * 16), "l"(src + q * 8));
        }
    }

    auto stage_kv = [&](int kt, int b) {
        const uint32_t sK = sbase + AOP + b * AOP;
        const uint32_t sV = sbase + 3 * AOP + b * AOP;
        #pragma unroll
        for (int p = 0; p < 2; p++) {
            int r = s_r + p * 64;
            const __half* srck = QKV + (rowbase + kt * 128 + r) * QKV_STR + hk;
            const __half* srcv = QKV + (rowbase + kt * 128 + r) * QKV_STR + hv;
            #pragma unroll
            for (int j = 0; j < 2; j++) {
                int q = s_q + j * 4;
                asm volatile("cp.async.cg.shared.global [%0], [%1], 16;\n"
                             :: "r"(sK + r * AROWB + q * 16), "l"(srck + q * 8));
                asm volatile("cp.async.cg.shared.global [%0], [%1], 16;\n"
                             :: "r"(sV + r * AROWB + q * 16), "l"(srcv + q * 8));
            }
        }
    };

    stage_kv(0, 0);
    asm volatile("cp.async.commit_group;\n");

    float accO[8][4];
    #pragma unroll
    for (int i = 0; i < 8; i++)
        #pragma unroll
        for (int j = 0; j < 4; j++) accO[i][j] = 0.0f;
    float m0 = -1e30f, m1 = -1e30f, l0 = 0.0f, l1 = 0.0f;

    int buf = 0;
    for (int kt = 0; kt <= qt; kt++) {
        asm volatile("cp.async.wait_group 0;\n");
        __syncthreads();
        if (kt < qt) {
            stage_kv(kt + 1, buf ^ 1);
            asm volatile("cp.async.commit_group;\n");
        }
        const uint32_t sK = sbase + AOP + buf * AOP;
        const uint32_t sV = sbase + 3 * AOP + buf * AOP;

        // ---- S = Q K^T (16 rows x 128 keys per warp) ----
        float accS[16][4];
        #pragma unroll
        for (int i = 0; i < 16; i++)
            #pragma unroll
            for (int j = 0; j < 4; j++) accS[i][j] = 0.0f;

        #pragma unroll
        for (int ko = 0; ko < 64; ko += 16) {
            uint32_t af[4];
            ldsm_x4(af, sQ + (wrow + (lane & 15)) * AROWB
                        + (ko + ((lane & 16) ? 8 : 0)) * 2);
            #pragma unroll
            for (int g = 0; g < 8; g++) {
                uint32_t kr[4];
                ldsm_x4(kr, sK + (g * 16 + (lane & 7) + ((lane & 16) ? 8 : 0)) * AROWB
                            + (ko + ((lane & 8) ? 8 : 0)) * 2);
                mma16816(accS[2 * g],     af, kr[0], kr[1]);
                mma16816(accS[2 * g + 1], af, kr[2], kr[3]);
            }
        }

        // ---- scale ----
        #pragma unroll
        for (int i = 0; i < 16; i++)
            #pragma unroll
            for (int j = 0; j < 4; j++) accS[i][j] *= scale;

        // ---- causal mask on diagonal tile ----
        if (kt == qt) {
            #pragma unroll
            for (int nt = 0; nt < 16; nt++) {
                int c = nt * 8 + 2 * tig;
                if (c     > rbase    ) accS[nt][0] = -1e30f;
                if (c + 1 > rbase    ) accS[nt][1] = -1e30f;
                if (c     > rbase + 8) accS[nt][2] = -1e30f;
                if (c + 1 > rbase + 8) accS[nt][3] = -1e30f;
            }
        }

        // ---- online softmax ----
        float mx0 = -1e30f, mx1 = -1e30f;
        #pragma unroll
        for (int nt = 0; nt < 16; nt++) {
            mx0 = fmaxf(mx0, fmaxf(accS[nt][0], accS[nt][1]));
            mx1 = fmaxf(mx1, fmaxf(accS[nt][2], accS[nt][3]));
        }
        mx0 = fmaxf(mx0, __shfl_xor_sync(0xffffffffu, mx0, 1));
        mx0 = fmaxf(mx0, __shfl_xor_sync(0xffffffffu, mx0, 2));
        mx1 = fmaxf(mx1, __shfl_xor_sync(0xffffffffu, mx1, 1));
        mx1 = fmaxf(mx1, __shfl_xor_sync(0xffffffffu, mx1, 2));

        float mn0 = fmaxf(m0, mx0), mn1 = fmaxf(m1, mx1);
        float al0 = __expf(m0 - mn0), al1 = __expf(m1 - mn1);
        m0 = mn0; m1 = mn1;

        float s0 = 0.0f, s1 = 0.0f;
        #pragma unroll
        for (int nt = 0; nt < 16; nt++) {
            float p0 = __expf(accS[nt][0] - mn0);
            float p1 = __expf(accS[nt][1] - mn0);
            float p2 = __expf(accS[nt][2] - mn1);
            float p3 = __expf(accS[nt][3] - mn1);
            accS[nt][0] = p0; accS[nt][1] = p1;
            accS[nt][2] = p2; accS[nt][3] = p3;
            s0 += p0 + p1; s1 += p2 + p3;
        }
        s0 += __shfl_xor_sync(0xffffffffu, s0, 1);
        s0 += __shfl_xor_sync(0xffffffffu, s0, 2);
        s1 += __shfl_xor_sync(0xffffffffu, s1, 1);
        s1 += __shfl_xor_sync(0xffffffffu, s1, 2);
        l0 = l0 * al0 + s0;
        l1 = l1 * al1 + s1;

        #pragma unroll
        for (int i = 0; i < 8; i++) {
            accO[i][0] *= al0; accO[i][1] *= al0;
            accO[i][2] *= al1; accO[i][3] *= al1;
        }

        // ---- O += P V ; P straight from registers (C-frag == A-frag) ----
        #pragma unroll
        for (int ki = 0; ki < 8; ki++) {
            uint32_t pa[4];
            pa[0] = f22h(accS[2 * ki][0],     accS[2 * ki][1]);
            pa[1] = f22h(accS[2 * ki][2],     accS[2 * ki][3]);
            pa[2] = f22h(accS[2 * ki + 1][0], accS[2 * ki + 1][1]);
            pa[3] = f22h(accS[2 * ki + 1][2], accS[2 * ki + 1][3]);
            #pragma unroll
            for (int dt = 0; dt < 4; dt++) {
                uint32_t vr[4];
                ldsm_x4t(vr, sV + (ki * 16 + (lane & 7) + ((lane & 8) ? 8 : 0)) * AROWB
                             + (dt * 16 + ((lane & 16) ? 8 : 0)) * 2);
                mma16816(accO[2 * dt],     pa, vr[0], vr[1]);
                mma16816(accO[2 * dt + 1], pa, vr[2], vr[3]);
            }
        }
        __syncthreads();
        buf ^= 1;
    }

    // ---- writeback ----
    float inv0 = 1.0f / l0, inv1 = 1.0f / l1;
    #pragma unroll
    for (int nt = 0; nt < 8; nt++) {
        int col = nt * 8 + 2 * tig;
        __half2 o0 = __floats2half2_rn(accO[nt][0] * inv0, accO[nt][1] * inv0);
        __half2 o1 = __floats2half2_rn(accO[nt][2] * inv1, accO[nt][3] * inv1);
        *(__half2*)(O + bout + (size_t)(qt * 128 + rbase    ) * E_DIM + col) = o0;
        *(__half2*)(O + bout + (size_t)(qt * 128 + rbase + 8) * E_DIM + col) = o1;
    }
}

// ---------------------------------------------------------------------------
// Residual add + LayerNorm (writes f32 + half copy)
// ---------------------------------------------------------------------------
__global__ __launch_bounds__(256)
void add_ln_kernel(const float* __restrict__ a, const float* __restrict__ b,
                   const float* __restrict__ g, const float* __restrict__ beta,
                   float* __restrict__ out, __half* __restrict__ outh)
{
    __shared__ float sred[256];
    int row = blockIdx.x;
    int tid = threadIdx.x;
    const float* ar = a + (size_t)row * E_DIM;
    const float* br = b + (size_t)row * E_DIM;
    float* orow = out + (size_t)row * E_DIM;
    __half* ohrow = outh + (size_t)row * E_DIM;

    float xv[4];
    float lsum = 0.0f;
    #pragma unroll
    for (int j = 0; j < 4; j++) {
        int e = tid + j * 256;
        xv[j] = ar[e] + br[e];
        lsum += xv[j];
    }
    sred[tid] = lsum;
    __syncthreads();
    #pragma unroll
    for (int s = 128; s > 0; s >>= 1) {
        if (tid < s) sred[tid] += sred[tid + s];
        __syncthreads();
    }
    float mean = sred[0] * (1.0f / E_DIM);
    __syncthreads();

    float lvar = 0.0f;
    #pragma unroll
    for (int j = 0; j < 4; j++) {
        float d = xv[j] - mean;
        lvar += d * d;
    }
    sred[tid] = lvar;
    __syncthreads();
    #pragma unroll
    for (int s = 128; s > 0; s >>= 1) {
        if (tid < s) sred[tid] += sred[tid + s];
        __syncthreads();
    }
    float rstd = rsqrtf(sred[0] * (1.0f / E_DIM) + 1e-5f);

    #pragma unroll
    for (int j = 0; j < 4; j++) {
        int e = tid + j * 256;
        float v = (xv[j] - mean) * rstd * g[e] + beta[e];
        orow[e] = v;
        ohrow[e] = __float2half_rn(v);
    }
}

// ---------------------------------------------------------------------------
// Launch
// ---------------------------------------------------------------------------
extern "C" void kernel_launch(void* const* d_in, const int* in_sizes, int n_in,
                              void* d_out, int out_size)
{
    const int*   x    = (const int*)  d_in[0];
    const float* emb  = (const float*)d_in[1];
    const float* Wq   = (const float*)d_in[2];
    const float* bq   = (const float*)d_in[3];
    const float* Wk   = (const float*)d_in[4];
    const float* bk   = (const float*)d_in[5];
    const float* Wv   = (const float*)d_in[6];
    const float* bv   = (const float*)d_in[7];
    const float* Wo   = (const float*)d_in[8];
    const float* bo   = (const float*)d_in[9];
    const float* ln1g = (const float*)d_in[10];
    const float* ln1b = (const float*)d_in[11];
    const float* ln2g = (const float*)d_in[12];
    const float* ln2b = (const float*)d_in[13];
    const float* W1   = (const float*)d_in[14];
    const float* b1   = (const float*)d_in[15];
    const float* W2   = (const float*)d_in[16];
    const float* b2   = (const float*)d_in[17];
    const float* Wout = (const float*)d_in[18];
    const float* bout = (const float*)d_in[19];
    float* out = (float*)d_out;

    float *act, *tmp, *hbuf, *bqkv;
    __half *act_h, *qkv_h, *attn_h, *h_h, *ff_h, *wh;
    cudaGetSymbolAddress((void**)&act,    g_act);
    cudaGetSymbolAddress((void**)&act_h,  g_act_h);
    cudaGetSymbolAddress((void**)&qkv_h,  g_qkv_h);
    cudaGetSymbolAddress((void**)&attn_h, g_attn_h);
    cudaGetSymbolAddress((void**)&tmp,    g_tmp);
    cudaGetSymbolAddress((void**)&hbuf,   g_h);
    cudaGetSymbolAddress((void**)&h_h,    g_h_h);
    cudaGetSymbolAddress((void**)&ff_h,   g_ff_h);
    cudaGetSymbolAddress((void**)&bqkv,   g_bqkv);
    cudaGetSymbolAddress((void**)&wh,     g_wh);

    static int attr_set = 0;
    if (!attr_set) {
        cudaFuncSetAttribute(flash_attn_h,
                             cudaFuncAttributeMaxDynamicSharedMemorySize, ATTN_SMEM);
        cudaFuncSetAttribute(hgemm4<0, 1, 0>,
                             cudaFuncAttributeMaxDynamicSharedMemorySize, GEMM_SMEM);
        cudaFuncSetAttribute(hgemm4<0, 0, 1>,
                             cudaFuncAttributeMaxDynamicSharedMemorySize, GEMM_SMEM);
        cudaFuncSetAttribute(hgemm4<1, 0, 1>,
                             cudaFuncAttributeMaxDynamicSharedMemorySize, GEMM_SMEM);
        attr_set = 1;
    }

    // ---- upfront: weight transposes (batched, vectorized) + bias pack ----
    {
        dim3 blk(32, 8);
        dim3 gEE(E_DIM / 32, E_DIM / 64, L_NUM);
        transpose_half_b2<<<gEE, blk>>>(Wq, wh + 0 * WO_LSTR, E_DIM, E_DIM,
                                        (size_t)E_DIM * E_DIM, QKV_LSTR);
        transpose_half_b2<<<gEE, blk>>>(Wk, wh + 1 * WO_LSTR, E_DIM, E_DIM,
                                        (size_t)E_DIM * E_DIM, QKV_LSTR);
        transpose_half_b2<<<gEE, blk>>>(Wv, wh + 2 * WO_LSTR, E_DIM, E_DIM,
                                        (size_t)E_DIM * E_DIM, QKV_LSTR);
        transpose_half_b2<<<gEE, blk>>>(Wo, wh + OFF_WO, E_DIM, E_DIM,
                                        (size_t)E_DIM * E_DIM, WO_LSTR);
        dim3 gW1(FF_DIM / 32, E_DIM / 64, L_NUM);
        transpose_half_b2<<<gW1, blk>>>(W1, wh + OFF_W1, E_DIM, FF_DIM,
                                        (size_t)E_DIM * FF_DIM, W1_LSTR);
        dim3 gW2(E_DIM / 32, FF_DIM / 64, L_NUM);
        transpose_half_b2<<<gW2, blk>>>(W2, wh + OFF_W2, FF_DIM, E_DIM,
                                        (size_t)FF_DIM * E_DIM, W2_LSTR);
        dim3 gWV(V_DIM / 32, E_DIM / 64, 1);
        transpose_half_b2<<<gWV, blk>>>(Wout, wh + OFF_WOUT, E_DIM, V_DIM,
                                        (size_t)E_DIM * V_DIM, 0);
        pack_qkv_bias<<<(L_NUM * QKV_STR) / 256, 256>>>(bq, bk, bv, bqkv);
    }

    embed_kernel<<<M_TOK, 256>>>(x, emb, act, act_h);

    for (int i = 0; i < L_NUM; i++) {
        size_t bo_off = (size_t)i * E_DIM;

        // QKV projection: half out only
        hgemm4<0, 0, 1><<<dim3(QKV_STR / GBN, M_TOK / GBM), 256, GEMM_SMEM>>>(
            act_h, wh + (size_t)i * QKV_LSTR, bqkv + (size_t)i * QKV_STR,
            (float*)0, qkv_h, QKV_STR, E_DIM);

        flash_attn_h<<<dim3(S_LEN / 128, H_DIM, N_B), 256, ATTN_SMEM>>>(qkv_h, attn_h);

        hgemm4<0, 1, 0><<<dim3(E_DIM / GBN, M_TOK / GBM), 256, GEMM_SMEM>>>(
            attn_h, wh + OFF_WO + (size_t)i * WO_LSTR, bo + bo_off,
            tmp, (__half*)0, E_DIM, E_DIM);

        add_ln_kernel<<<M_TOK, 256>>>(tmp, act, ln1g + bo_off, ln1b + bo_off,
                                      hbuf, h_h);

        hgemm4<1, 0, 1><<<dim3(FF_DIM / GBN, M_TOK / GBM), 256, GEMM_SMEM>>>(
            h_h, wh + OFF_W1 + (size_t)i * W1_LSTR, b1 + (size_t)i * FF_DIM,
            (float*)0, ff_h, FF_DIM, E_DIM);

        hgemm4<0, 1, 0><<<dim3(E_DIM / GBN, M_TOK / GBM), 256, GEMM_SMEM>>>(
            ff_h, wh + OFF_W2 + (size_t)i * W2_LSTR, b2 + bo_off,
            tmp, (__half*)0, E_DIM, FF_DIM);

        add_ln_kernel<<<M_TOK, 256>>>(tmp, hbuf, ln2g + bo_off, ln2b + bo_off,
                                      act, act_h);
    }

    hgemm4<0, 1, 0><<<dim3(V_DIM / GBN, M_TOK / GBM), 256, GEMM_SMEM>>>(
        act_h, wh + OFF_WOUT, bout, out, (__half*)0, V_DIM, E_DIM);
}

// round 13
// speedup vs baseline: 1.3379x; 1.0500x over previous
#include <cuda_runtime.h>
#include <cuda_fp16.h>
#include <math.h>
#include <stdint.h>

#define E_DIM 1024
#define H_DIM 16
#define D_DIM 64
#define S_LEN 1024
#define N_B   4
#define L_NUM 4
#define FF_DIM 4096
#define V_DIM 32000
#define M_TOK (N_B * S_LEN)   // 4096 token rows
#define QKV_STR (3 * E_DIM)   // 3072

// ---------------------------------------------------------------------------
// Transposed-weight half buffer layout (element offsets)
// ---------------------------------------------------------------------------
#define QKV_LSTR   (3 * E_DIM * E_DIM)
#define OFF_WO     (L_NUM * QKV_LSTR)
#define WO_LSTR    (E_DIM * E_DIM)
#define OFF_W1     (OFF_WO + L_NUM * WO_LSTR)
#define W1_LSTR    (E_DIM * FF_DIM)
#define OFF_W2     (OFF_W1 + L_NUM * W1_LSTR)
#define W2_LSTR    (FF_DIM * E_DIM)
#define OFF_WOUT   (OFF_W2 + L_NUM * W2_LSTR)
#define WH_TOTAL   (OFF_WOUT + (size_t)V_DIM * E_DIM)

// ---------------------------------------------------------------------------
// Scratch (device globals; no allocations allowed)
// ---------------------------------------------------------------------------
__device__ float  g_act  [M_TOK * E_DIM];
__device__ __half g_act_h[M_TOK * E_DIM];
__device__ __half g_qkv_h[M_TOK * QKV_STR];
__device__ __half g_attn_h[M_TOK * E_DIM];
__device__ float  g_tmp  [M_TOK * E_DIM];
__device__ float  g_h    [M_TOK * E_DIM];
__device__ __half g_h_h  [M_TOK * E_DIM];
__device__ __half g_ff_h [M_TOK * FF_DIM];
__device__ float  g_bqkv [L_NUM * QKV_STR];
__device__ __half g_wh   [WH_TOTAL];

__device__ __forceinline__ uint32_t smem_u32(const void* p) {
    uint32_t a;
    asm("{ .reg .u64 t; cvta.to.shared.u64 t, %1; cvt.u32.u64 %0, t; }"
        : "=r"(a) : "l"(p));
    return a;
}

__device__ __forceinline__ void ldsm_x4(uint32_t* r, uint32_t addr) {
    asm volatile("ldmatrix.sync.aligned.m8n8.x4.shared.b16 {%0,%1,%2,%3}, [%4];"
                 : "=r"(r[0]), "=r"(r[1]), "=r"(r[2]), "=r"(r[3]) : "r"(addr));
}
__device__ __forceinline__ void ldsm_x4t(uint32_t* r, uint32_t addr) {
    asm volatile("ldmatrix.sync.aligned.m8n8.x4.trans.shared.b16 {%0,%1,%2,%3}, [%4];"
                 : "=r"(r[0]), "=r"(r[1]), "=r"(r[2]), "=r"(r[3]) : "r"(addr));
}
__device__ __forceinline__ void mma16816(float* c, const uint32_t* a,
                                         uint32_t b0, uint32_t b1) {
    asm volatile(
        "mma.sync.aligned.m16n8k16.row.col.f32.f16.f16.f32 "
        "{%0,%1,%2,%3}, {%4,%5,%6,%7}, {%8,%9}, {%0,%1,%2,%3};\n"
        : "+f"(c[0]), "+f"(c[1]), "+f"(c[2]), "+f"(c[3])
        : "r"(a[0]), "r"(a[1]), "r"(a[2]), "r"(a[3]), "r"(b0), "r"(b1));
}
__device__ __forceinline__ uint32_t f22h(float a, float b) {
    __half2 h = __floats2half2_rn(a, b);
    return *(uint32_t*)&h;
}

// ---------------------------------------------------------------------------
// Embedding + sinusoidal positional encoding (writes f32 + half copies)
// ---------------------------------------------------------------------------
__global__ void embed_kernel(const int* __restrict__ x,
                             const float* __restrict__ emb,
                             float* __restrict__ out,
                             __half* __restrict__ outh)
{
    int row = blockIdx.x;
    int s   = row & (S_LEN - 1);
    int tok = x[row];
    const float* erow = emb + (size_t)tok * E_DIM;
    float* orow = out + (size_t)row * E_DIM;
    __half* ohrow = outh + (size_t)row * E_DIM;

    int e0 = threadIdx.x * 4;
    #pragma unroll
    for (int j = 0; j < 4; j++) {
        int e = e0 + j;
        int even = e & ~1;
        float expo = (float)even / (float)E_DIM;
        float denom = powf(10000.0f, expo);
        float ang = (float)s / denom;
        float pe = (e & 1) ? cosf(ang) : sinf(ang);
        float v = erow[e] + pe;
        orow[e] = v;
        ohrow[e] = __float2half_rn(v);
    }
}

// ---------------------------------------------------------------------------
// Batched transpose+half, 64x64 tiles, swizzled SMEM (2-way max conflicts).
// Dz[n][k] = half(Wz[k][n]); block (32,8); grid (N/64, K/64, L)
// ---------------------------------------------------------------------------
__global__ __launch_bounds__(256)
void transpose_half_b3(const float* __restrict__ W, __half* __restrict__ dst,
                       int Kd, int Nd, size_t src_stride, size_t dst_stride)
{
    __shared__ float tile[64][64];
    const float* Wz = W + (size_t)blockIdx.z * src_stride;
    __half* Dz = dst + (size_t)blockIdx.z * dst_stride;
    int n0 = blockIdx.x * 64, k0 = blockIdx.y * 64;
    int tx = threadIdx.x, ty = threadIdx.y;
    #pragma unroll
    for (int i = 0; i < 8; i++) {
        int r = ty + 8 * i;
        float2 v = *(const float2*)(Wz + (size_t)(k0 + r) * Nd + n0 + 2 * tx);
        tile[r][(2 * tx + r) & 63]     = v.x;
        tile[r][(2 * tx + 1 + r) & 63] = v.y;
    }
    __syncthreads();
    #pragma unroll
    for (int i = 0; i < 8; i++) {
        int nr = ty + 8 * i;
        float a = tile[2 * tx    ][(nr + 2 * tx)     & 63];
        float b = tile[2 * tx + 1][(nr + 2 * tx + 1) & 63];
        *(__half2*)(Dz + (size_t)(n0 + nr) * Kd + k0 + 2 * tx) =
            __floats2half2_rn(a, b);
    }
}

__global__ void pack_qkv_bias(const float* __restrict__ bq,
                              const float* __restrict__ bk,
                              const float* __restrict__ bv,
                              float* __restrict__ out)
{
    int i = blockIdx.x * 256 + threadIdx.x;
    int layer = i / QKV_STR, c = i % QKV_STR;
    float v;
    if (c < E_DIM)           v = bq[layer * E_DIM + c];
    else if (c < 2 * E_DIM)  v = bk[layer * E_DIM + c - E_DIM];
    else                     v = bv[layer * E_DIM + c - 2 * E_DIM];
    out[i] = v;
}

// ---------------------------------------------------------------------------
// FP16 GEMM: CTA 128x128, warp 64x32, BK=32, ROWB=112, 3-stage cp.async,
// 2 CTAs/SM. A[M][K] half, Bt[N][K] half, f32 accum.
// B fragments via 2x ldsm_x4 (16-row groups). Optional fused residual add.
// ---------------------------------------------------------------------------
#define GBM 128
#define GBN 128
#define GBK 32
#define ROWB 112
#define OP_ST (128 * ROWB)
#define STG   (2 * OP_ST)
#define NST   3
#define GEMM_SMEM (NST * STG)

template<int RELU, int WF, int WH, int ADDR>
__global__ __launch_bounds__(256, 2)
void hgemm5(const __half* __restrict__ A, const __half* __restrict__ Bt,
            const float* __restrict__ bias, const float* __restrict__ Rf,
            float* __restrict__ Cf, __half* __restrict__ Ch,
            int Nd, int Kd)
{
    extern __shared__ char smem[];
    const uint32_t sbase = smem_u32(smem);

    const int tid  = threadIdx.x;
    const int lane = tid & 31;
    const int wid  = tid >> 5;
    const int gid  = lane >> 2;
    const int tig  = lane & 3;

    const int m0 = blockIdx.y * GBM;
    const int n0 = blockIdx.x * GBN;
    const int wm = (wid >> 2) * 64;
    const int wn = (wid & 3) * 32;

    const int arow   = wm + (lane & 15);
    const int akoh   = (lane & 16) ? 8 : 0;
    const int brow16 = wn + (lane & 7) + ((lane & 16) ? 8 : 0);
    const int bkoh   = (lane & 8) ? 8 : 0;

    const int s_row = tid >> 2;
    const int s_q   = tid & 3;

    float acc[4][4][4];
    #pragma unroll
    for (int i = 0; i < 4; i++)
        #pragma unroll
        for (int j = 0; j < 4; j++)
            #pragma unroll
            for (int r = 0; r < 4; r++) acc[i][j][r] = 0.0f;

    const int nK = Kd / GBK;

    auto issue_stage = [&](int t, int buf) {
        const uint32_t base = sbase + buf * STG;
        const __half* Ag = A + (size_t)m0 * Kd + t * GBK;
        const __half* Bg = Bt + (size_t)n0 * Kd + t * GBK;
        #pragma unroll
        for (int p = 0; p < 2; p++) {
            int r = s_row + p * 64;
            uint32_t da = base + r * ROWB + s_q * 16;
            const __half* sa = Ag + (size_t)r * Kd + s_q * 8;
            asm volatile("cp.async.cg.shared.global [%0], [%1], 16;\n"
                         :: "r"(da), "l"(sa));
            uint32_t db = base + OP_ST + r * ROWB + s_q * 16;
            const __half* sb = Bg + (size_t)r * Kd + s_q * 8;
            asm volatile("cp.async.cg.shared.global [%0], [%1], 16;\n"
                         :: "r"(db), "l"(sb));
        }
        asm volatile("cp.async.commit_group;\n");
    };

    issue_stage(0, 0);
    if (nK > 1) issue_stage(1, 1);

    int buf = 0;
    for (int t = 0; t < nK; t++) {
        if (t + 1 < nK) asm volatile("cp.async.wait_group 1;\n");
        else            asm volatile("cp.async.wait_group 0;\n");
        __syncthreads();

        if (t + 2 < nK) {
            int nb = buf + 2; if (nb >= NST) nb -= NST;
            issue_stage(t + 2, nb);
        }

        const uint32_t sA = sbase + buf * STG;
        const uint32_t sB = sA + OP_ST;
        #pragma unroll
        for (int ko = 0; ko < GBK; ko += 16) {
            uint32_t af[4][4], bf[4][2];
            #pragma unroll
            for (int mt = 0; mt < 4; mt++)
                ldsm_x4(af[mt], sA + (arow + mt * 16) * ROWB + (ko + akoh) * 2);
            #pragma unroll
            for (int g = 0; g < 2; g++) {
                uint32_t r[4];
                ldsm_x4(r, sB + (brow16 + g * 16) * ROWB + (ko + bkoh) * 2);
                bf[2 * g][0] = r[0]; bf[2 * g][1] = r[1];
                bf[2 * g + 1][0] = r[2]; bf[2 * g + 1][1] = r[3];
            }
            #pragma unroll
            for (int mt = 0; mt < 4; mt++)
                #pragma unroll
                for (int nt = 0; nt < 4; nt++)
                    mma16816(acc[mt][nt], af[mt], bf[nt][0], bf[nt][1]);
        }
        if (++buf >= NST) buf = 0;
    }

    #pragma unroll
    for (int nt = 0; nt < 4; nt++) {
        int col = n0 + wn + nt * 8 + 2 * tig;
        float b0 = bias[col];
        float b1 = bias[col + 1];
        #pragma unroll
        for (int mt = 0; mt < 4; mt++) {
            int row = m0 + wm + mt * 16 + gid;
            float v00 = acc[mt][nt][0] + b0;
            float v01 = acc[mt][nt][1] + b1;
            float v10 = acc[mt][nt][2] + b0;
            float v11 = acc[mt][nt][3] + b1;
            if (ADDR) {
                float2 r0 = *(const float2*)(Rf + (size_t)row * Nd + col);
                float2 r1 = *(const float2*)(Rf + (size_t)(row + 8) * Nd + col);
                v00 += r0.x; v01 += r0.y;
                v10 += r1.x; v11 += r1.y;
            }
            if (RELU) {
                v00 = fmaxf(v00, 0.0f); v01 = fmaxf(v01, 0.0f);
                v10 = fmaxf(v10, 0.0f); v11 = fmaxf(v11, 0.0f);
            }
            if (WF) {
                float2 f0 = {v00, v01}, f1 = {v10, v11};
                *(float2*)(Cf + (size_t)row * Nd + col)       = f0;
                *(float2*)(Cf + (size_t)(row + 8) * Nd + col) = f1;
            }
            if (WH) {
                __half2 h0 = __floats2half2_rn(v00, v01);
                __half2 h1 = __floats2half2_rn(v10, v11);
                *(__half2*)(Ch + (size_t)row * Nd + col)       = h0;
                *(__half2*)(Ch + (size_t)(row + 8) * Nd + col) = h1;
            }
        }
    }
}

// ---------------------------------------------------------------------------
// FP16 flash attention (round-12, unchanged)
// ---------------------------------------------------------------------------
#define AROWB 144
#define AOP   (128 * AROWB)
#define ATTN_SMEM (5 * AOP)

__global__ __launch_bounds__(256)
void flash_attn_h(const __half* __restrict__ QKV, __half* __restrict__ O)
{
    extern __shared__ char smem[];
    const uint32_t sbase = smem_u32(smem);
    const uint32_t sQ = sbase;

    const int tid  = threadIdx.x;
    const int lane = tid & 31;
    const int wid  = tid >> 5;
    const int gid  = lane >> 2;
    const int tig  = lane & 3;

    const int qt = gridDim.x - 1 - blockIdx.x;
    const int h  = blockIdx.y;
    const int n  = blockIdx.z;
    const size_t rowbase = (size_t)n * S_LEN;
    const int hq = h * D_DIM;
    const int hk = E_DIM + h * D_DIM;
    const int hv = 2 * E_DIM + h * D_DIM;
    const size_t bout = rowbase * E_DIM + h * D_DIM;
    const float scale = 1.0f / 32.0f;
    const int wrow = wid * 16;
    const int rbase = wrow + gid;

    const int s_r = tid >> 2;
    const int s_q = tid & 3;

    #pragma unroll
    for (int p = 0; p < 2; p++) {
        int r = s_r + p * 64;
        const __half* src = QKV + (rowbase + qt * 128 + r) * QKV_STR + hq;
        #pragma unroll
        for (int j = 0; j < 2; j++) {
            int q = s_q + j * 4;
            asm volatile("cp.async.cg.shared.global [%0], [%1], 16;\n"
                         :: "r"(sQ + r * AROWB + q * 16), "l"(src + q * 8));
        }
    }

    auto stage_kv = [&](int kt, int b) {
        const uint32_t sK = sbase + AOP + b * AOP;
        const uint32_t sV = sbase + 3 * AOP + b * AOP;
        #pragma unroll
        for (int p = 0; p < 2; p++) {
            int r = s_r + p * 64;
            const __half* srck = QKV + (rowbase + kt * 128 + r) * QKV_STR + hk;
            const __half* srcv = QKV + (rowbase + kt * 128 + r) * QKV_STR + hv;
            #pragma unroll
            for (int j = 0; j < 2; j++) {
                int q = s_q + j * 4;
                asm volatile("cp.async.cg.shared.global [%0], [%1], 16;\n"
                             :: "r"(sK + r * AROWB + q * 16), "l"(srck + q * 8));
                asm volatile("cp.async.cg.shared.global [%0], [%1], 16;\n"
                             :: "r"(sV + r * AROWB + q * 16), "l"(srcv + q * 8));
            }
        }
    };

    stage_kv(0, 0);
    asm volatile("cp.async.commit_group;\n");

    float accO[8][4];
    #pragma unroll
    for (int i = 0; i < 8; i++)
        #pragma unroll
        for (int j = 0; j < 4; j++) accO[i][j] = 0.0f;
    float m0 = -1e30f, m1 = -1e30f, l0 = 0.0f, l1 = 0.0f;

    int buf = 0;
    for (int kt = 0; kt <= qt; kt++) {
        asm volatile("cp.async.wait_group 0;\n");
        __syncthreads();
        if (kt < qt) {
            stage_kv(kt + 1, buf ^ 1);
            asm volatile("cp.async.commit_group;\n");
        }
        const uint32_t sK = sbase + AOP + buf * AOP;
        const uint32_t sV = sbase + 3 * AOP + buf * AOP;

        float accS[16][4];
        #pragma unroll
        for (int i = 0; i < 16; i++)
            #pragma unroll
            for (int j = 0; j < 4; j++) accS[i][j] = 0.0f;

        #pragma unroll
        for (int ko = 0; ko < 64; ko += 16) {
            uint32_t af[4];
            ldsm_x4(af, sQ + (wrow + (lane & 15)) * AROWB
                        + (ko + ((lane & 16) ? 8 : 0)) * 2);
            #pragma unroll
            for (int g = 0; g < 8; g++) {
                uint32_t kr[4];
                ldsm_x4(kr, sK + (g * 16 + (lane & 7) + ((lane & 16) ? 8 : 0)) * AROWB
                            + (ko + ((lane & 8) ? 8 : 0)) * 2);
                mma16816(accS[2 * g],     af, kr[0], kr[1]);
                mma16816(accS[2 * g + 1], af, kr[2], kr[3]);
            }
        }

        #pragma unroll
        for (int i = 0; i < 16; i++)
            #pragma unroll
            for (int j = 0; j < 4; j++) accS[i][j] *= scale;

        if (kt == qt) {
            #pragma unroll
            for (int nt = 0; nt < 16; nt++) {
                int c = nt * 8 + 2 * tig;
                if (c     > rbase    ) accS[nt][0] = -1e30f;
                if (c + 1 > rbase    ) accS[nt][1] = -1e30f;
                if (c     > rbase + 8) accS[nt][2] = -1e30f;
                if (c + 1 > rbase + 8) accS[nt][3] = -1e30f;
            }
        }

        float mx0 = -1e30f, mx1 = -1e30f;
        #pragma unroll
        for (int nt = 0; nt < 16; nt++) {
            mx0 = fmaxf(mx0, fmaxf(accS[nt][0], accS[nt][1]));
            mx1 = fmaxf(mx1, fmaxf(accS[nt][2], accS[nt][3]));
        }
        mx0 = fmaxf(mx0, __shfl_xor_sync(0xffffffffu, mx0, 1));
        mx0 = fmaxf(mx0, __shfl_xor_sync(0xffffffffu, mx0, 2));
        mx1 = fmaxf(mx1, __shfl_xor_sync(0xffffffffu, mx1, 1));
        mx1 = fmaxf(mx1, __shfl_xor_sync(0xffffffffu, mx1, 2));

        float mn0 = fmaxf(m0, mx0), mn1 = fmaxf(m1, mx1);
        float al0 = __expf(m0 - mn0), al1 = __expf(m1 - mn1);
        m0 = mn0; m1 = mn1;

        float s0 = 0.0f, s1 = 0.0f;
        #pragma unroll
        for (int nt = 0; nt < 16; nt++) {
            float p0 = __expf(accS[nt][0] - mn0);
            float p1 = __expf(accS[nt][1] - mn0);
            float p2 = __expf(accS[nt][2] - mn1);
            float p3 = __expf(accS[nt][3] - mn1);
            accS[nt][0] = p0; accS[nt][1] = p1;
            accS[nt][2] = p2; accS[nt][3] = p3;
            s0 += p0 + p1; s1 += p2 + p3;
        }
        s0 += __shfl_xor_sync(0xffffffffu, s0, 1);
        s0 += __shfl_xor_sync(0xffffffffu, s0, 2);
        s1 += __shfl_xor_sync(0xffffffffu, s1, 1);
        s1 += __shfl_xor_sync(0xffffffffu, s1, 2);
        l0 = l0 * al0 + s0;
        l1 = l1 * al1 + s1;

        #pragma unroll
        for (int i = 0; i < 8; i++) {
            accO[i][0] *= al0; accO[i][1] *= al0;
            accO[i][2] *= al1; accO[i][3] *= al1;
        }

        #pragma unroll
        for (int ki = 0; ki < 8; ki++) {
            uint32_t pa[4];
            pa[0] = f22h(accS[2 * ki][0],     accS[2 * ki][1]);
            pa[1] = f22h(accS[2 * ki][2],     accS[2 * ki][3]);
            pa[2] = f22h(accS[2 * ki + 1][0], accS[2 * ki + 1][1]);
            pa[3] = f22h(accS[2 * ki + 1][2], accS[2 * ki + 1][3]);
            #pragma unroll
            for (int dt = 0; dt < 4; dt++) {
                uint32_t vr[4];
                ldsm_x4t(vr, sV + (ki * 16 + (lane & 7) + ((lane & 8) ? 8 : 0)) * AROWB
                             + (dt * 16 + ((lane & 16) ? 8 : 0)) * 2);
                mma16816(accO[2 * dt],     pa, vr[0], vr[1]);
                mma16816(accO[2 * dt + 1], pa, vr[2], vr[3]);
            }
        }
        __syncthreads();
        buf ^= 1;
    }

    float inv0 = 1.0f / l0, inv1 = 1.0f / l1;
    #pragma unroll
    for (int nt = 0; nt < 8; nt++) {
        int col = nt * 8 + 2 * tig;
        __half2 o0 = __floats2half2_rn(accO[nt][0] * inv0, accO[nt][1] * inv0);
        __half2 o1 = __floats2half2_rn(accO[nt][2] * inv1, accO[nt][3] * inv1);
        *(__half2*)(O + bout + (size_t)(qt * 128 + rbase    ) * E_DIM + col) = o0;
        *(__half2*)(O + bout + (size_t)(qt * 128 + rbase + 8) * E_DIM + col) = o1;
    }
}

// ---------------------------------------------------------------------------
// LayerNorm over precomputed x (residual already fused into GEMM epilogue).
// Writes f32 + half copies.
// ---------------------------------------------------------------------------
__global__ __launch_bounds__(256)
void ln_kernel(const float* __restrict__ xin,
               const float* __restrict__ g, const float* __restrict__ beta,
               float* __restrict__ out, __half* __restrict__ outh)
{
    __shared__ float sred[256];
    int row = blockIdx.x;
    int tid = threadIdx.x;
    const float* xr = xin + (size_t)row * E_DIM;
    float* orow = out + (size_t)row * E_DIM;
    __half* ohrow = outh + (size_t)row * E_DIM;

    float xv[4];
    float lsum = 0.0f;
    #pragma unroll
    for (int j = 0; j < 4; j++) {
        int e = tid + j * 256;
        xv[j] = xr[e];
        lsum += xv[j];
    }
    sred[tid] = lsum;
    __syncthreads();
    #pragma unroll
    for (int s = 128; s > 0; s >>= 1) {
        if (tid < s) sred[tid] += sred[tid + s];
        __syncthreads();
    }
    float mean = sred[0] * (1.0f / E_DIM);
    __syncthreads();

    float lvar = 0.0f;
    #pragma unroll
    for (int j = 0; j < 4; j++) {
        float d = xv[j] - mean;
        lvar += d * d;
    }
    sred[tid] = lvar;
    __syncthreads();
    #pragma unroll
    for (int s = 128; s > 0; s >>= 1) {
        if (tid < s) sred[tid] += sred[tid + s];
        __syncthreads();
    }
    float rstd = rsqrtf(sred[0] * (1.0f / E_DIM) + 1e-5f);

    #pragma unroll
    for (int j = 0; j < 4; j++) {
        int e = tid + j * 256;
        float v = (xv[j] - mean) * rstd * g[e] + beta[e];
        orow[e] = v;
        ohrow[e] = __float2half_rn(v);
    }
}

// ---------------------------------------------------------------------------
// Launch
// ---------------------------------------------------------------------------
extern "C" void kernel_launch(void* const* d_in, const int* in_sizes, int n_in,
                              void* d_out, int out_size)
{
    const int*   x    = (const int*)  d_in[0];
    const float* emb  = (const float*)d_in[1];
    const float* Wq   = (const float*)d_in[2];
    const float* bq   = (const float*)d_in[3];
    const float* Wk   = (const float*)d_in[4];
    const float* bk   = (const float*)d_in[5];
    const float* Wv   = (const float*)d_in[6];
    const float* bv   = (const float*)d_in[7];
    const float* Wo   = (const float*)d_in[8];
    const float* bo   = (const float*)d_in[9];
    const float* ln1g = (const float*)d_in[10];
    const float* ln1b = (const float*)d_in[11];
    const float* ln2g = (const float*)d_in[12];
    const float* ln2b = (const float*)d_in[13];
    const float* W1   = (const float*)d_in[14];
    const float* b1   = (const float*)d_in[15];
    const float* W2   = (const float*)d_in[16];
    const float* b2   = (const float*)d_in[17];
    const float* Wout = (const float*)d_in[18];
    const float* bout = (const float*)d_in[19];
    float* out = (float*)d_out;

    float *act, *tmp, *hbuf, *bqkv;
    __half *act_h, *qkv_h, *attn_h, *h_h, *ff_h, *wh;
    cudaGetSymbolAddress((void**)&act,    g_act);
    cudaGetSymbolAddress((void**)&act_h,  g_act_h);
    cudaGetSymbolAddress((void**)&qkv_h,  g_qkv_h);
    cudaGetSymbolAddress((void**)&attn_h, g_attn_h);
    cudaGetSymbolAddress((void**)&tmp,    g_tmp);
    cudaGetSymbolAddress((void**)&hbuf,   g_h);
    cudaGetSymbolAddress((void**)&h_h,    g_h_h);
    cudaGetSymbolAddress((void**)&ff_h,   g_ff_h);
    cudaGetSymbolAddress((void**)&bqkv,   g_bqkv);
    cudaGetSymbolAddress((void**)&wh,     g_wh);

    static int attr_set = 0;
    if (!attr_set) {
        cudaFuncSetAttribute(flash_attn_h,
                             cudaFuncAttributeMaxDynamicSharedMemorySize, ATTN_SMEM);
        cudaFuncSetAttribute(hgemm5<0, 0, 1, 0>,
                             cudaFuncAttributeMaxDynamicSharedMemorySize, GEMM_SMEM);
        cudaFuncSetAttribute(hgemm5<1, 0, 1, 0>,
                             cudaFuncAttributeMaxDynamicSharedMemorySize, GEMM_SMEM);
        cudaFuncSetAttribute(hgemm5<0, 1, 0, 1>,
                             cudaFuncAttributeMaxDynamicSharedMemorySize, GEMM_SMEM);
        cudaFuncSetAttribute(hgemm5<0, 1, 0, 0>,
                             cudaFuncAttributeMaxDynamicSharedMemorySize, GEMM_SMEM);
        attr_set = 1;
    }

    // ---- upfront: weight transposes (batched, swizzled) + bias pack ----
    {
        dim3 blk(32, 8);
        dim3 gEE(E_DIM / 64, E_DIM / 64, L_NUM);
        transpose_half_b3<<<gEE, blk>>>(Wq, wh + 0 * WO_LSTR, E_DIM, E_DIM,
                                        (size_t)E_DIM * E_DIM, QKV_LSTR);
        transpose_half_b3<<<gEE, blk>>>(Wk, wh + 1 * WO_LSTR, E_DIM, E_DIM,
                                        (size_t)E_DIM * E_DIM, QKV_LSTR);
        transpose_half_b3<<<gEE, blk>>>(Wv, wh + 2 * WO_LSTR, E_DIM, E_DIM,
                                        (size_t)E_DIM * E_DIM, QKV_LSTR);
        transpose_half_b3<<<gEE, blk>>>(Wo, wh + OFF_WO, E_DIM, E_DIM,
                                        (size_t)E_DIM * E_DIM, WO_LSTR);
        dim3 gW1(FF_DIM / 64, E_DIM / 64, L_NUM);
        transpose_half_b3<<<gW1, blk>>>(W1, wh + OFF_W1, E_DIM, FF_DIM,
                                        (size_t)E_DIM * FF_DIM, W1_LSTR);
        dim3 gW2(E_DIM / 64, FF_DIM / 64, L_NUM);
        transpose_half_b3<<<gW2, blk>>>(W2, wh + OFF_W2, FF_DIM, E_DIM,
                                        (size_t)FF_DIM * E_DIM, W2_LSTR);
        dim3 gWV(V_DIM / 64, E_DIM / 64, 1);
        transpose_half_b3<<<gWV, blk>>>(Wout, wh + OFF_WOUT, E_DIM, V_DIM,
                                        (size_t)E_DIM * V_DIM, 0);
        pack_qkv_bias<<<(L_NUM * QKV_STR) / 256, 256>>>(bq, bk, bv, bqkv);
    }

    embed_kernel<<<M_TOK, 256>>>(x, emb, act, act_h);

    for (int i = 0; i < L_NUM; i++) {
        size_t bo_off = (size_t)i * E_DIM;

        // QKV projection: half out
        hgemm5<0, 0, 1, 0><<<dim3(QKV_STR / GBN, M_TOK / GBM), 256, GEMM_SMEM>>>(
            act_h, wh + (size_t)i * QKV_LSTR, bqkv + (size_t)i * QKV_STR,
            (const float*)0, (float*)0, qkv_h, QKV_STR, E_DIM);

        flash_attn_h<<<dim3(S_LEN / 128, H_DIM, N_B), 256, ATTN_SMEM>>>(qkv_h, attn_h);

        // Wo GEMM + fused residual (act): x1 -> tmp (f32)
        hgemm5<0, 1, 0, 1><<<dim3(E_DIM / GBN, M_TOK / GBM), 256, GEMM_SMEM>>>(
            attn_h, wh + OFF_WO + (size_t)i * WO_LSTR, bo + bo_off,
            act, tmp, (__half*)0, E_DIM, E_DIM);

        ln_kernel<<<M_TOK, 256>>>(tmp, ln1g + bo_off, ln1b + bo_off, hbuf, h_h);

        // FF1: half out (ReLU)
        hgemm5<1, 0, 1, 0><<<dim3(FF_DIM / GBN, M_TOK / GBM), 256, GEMM_SMEM>>>(
            h_h, wh + OFF_W1 + (size_t)i * W1_LSTR, b1 + (size_t)i * FF_DIM,
            (const float*)0, (float*)0, ff_h, FF_DIM, E_DIM);

        // FF2 + fused residual (hbuf): x2 -> tmp (f32)
        hgemm5<0, 1, 0, 1><<<dim3(E_DIM / GBN, M_TOK / GBM), 256, GEMM_SMEM>>>(
            ff_h, wh + OFF_W2 + (size_t)i * W2_LSTR, b2 + bo_off,
            hbuf, tmp, (__half*)0, E_DIM, FF_DIM);

        ln_kernel<<<M_TOK, 256>>>(tmp, ln2g + bo_off, ln2b + bo_off, act, act_h);
    }

    hgemm5<0, 1, 0, 0><<<dim3(V_DIM / GBN, M_TOK / GBM), 256, GEMM_SMEM>>>(
        act_h, wh + OFF_WOUT, bout, (const float*)0, out, (__half*)0, V_DIM, E_DIM);
}

// round 14
// speedup vs baseline: 1.3620x; 1.0180x over previous
#include <cuda_runtime.h>
#include <cuda_fp16.h>
#include <math.h>
#include <stdint.h>

#define E_DIM 1024
#define H_DIM 16
#define D_DIM 64
#define S_LEN 1024
#define N_B   4
#define L_NUM 4
#define FF_DIM 4096
#define V_DIM 32000
#define M_TOK (N_B * S_LEN)   // 4096 token rows
#define QKV_STR (3 * E_DIM)   // 3072

// ---------------------------------------------------------------------------
// Transposed-weight half buffer layout (element offsets)
// ---------------------------------------------------------------------------
#define QKV_LSTR   (3 * E_DIM * E_DIM)
#define OFF_WO     (L_NUM * QKV_LSTR)
#define WO_LSTR    (E_DIM * E_DIM)
#define OFF_W1     (OFF_WO + L_NUM * WO_LSTR)
#define W1_LSTR    (E_DIM * FF_DIM)
#define OFF_W2     (OFF_W1 + L_NUM * W1_LSTR)
#define W2_LSTR    (FF_DIM * E_DIM)
#define OFF_WOUT   (OFF_W2 + L_NUM * W2_LSTR)
#define WH_TOTAL   (OFF_WOUT + (size_t)V_DIM * E_DIM)

// ---------------------------------------------------------------------------
// Scratch (device globals; no allocations allowed)
// ---------------------------------------------------------------------------
__device__ float  g_act  [M_TOK * E_DIM];
__device__ __half g_act_h[M_TOK * E_DIM];
__device__ __half g_qkv_h[M_TOK * QKV_STR];
__device__ __half g_attn_h[M_TOK * E_DIM];
__device__ float  g_tmp  [M_TOK * E_DIM];
__device__ float  g_h    [M_TOK * E_DIM];
__device__ __half g_h_h  [M_TOK * E_DIM];
__device__ __half g_ff_h [M_TOK * FF_DIM];
__device__ float  g_bqkv [L_NUM * QKV_STR];
__device__ __half g_wh   [WH_TOTAL];

__device__ __forceinline__ uint32_t smem_u32(const void* p) {
    uint32_t a;
    asm("{ .reg .u64 t; cvta.to.shared.u64 t, %1; cvt.u32.u64 %0, t; }"
        : "=r"(a) : "l"(p));
    return a;
}

__device__ __forceinline__ void ldsm_x4(uint32_t* r, uint32_t addr) {
    asm volatile("ldmatrix.sync.aligned.m8n8.x4.shared.b16 {%0,%1,%2,%3}, [%4];"
                 : "=r"(r[0]), "=r"(r[1]), "=r"(r[2]), "=r"(r[3]) : "r"(addr));
}
__device__ __forceinline__ void ldsm_x4t(uint32_t* r, uint32_t addr) {
    asm volatile("ldmatrix.sync.aligned.m8n8.x4.trans.shared.b16 {%0,%1,%2,%3}, [%4];"
                 : "=r"(r[0]), "=r"(r[1]), "=r"(r[2]), "=r"(r[3]) : "r"(addr));
}
__device__ __forceinline__ void mma16816(float* c, const uint32_t* a,
                                         uint32_t b0, uint32_t b1) {
    asm volatile(
        "mma.sync.aligned.m16n8k16.row.col.f32.f16.f16.f32 "
        "{%0,%1,%2,%3}, {%4,%5,%6,%7}, {%8,%9}, {%0,%1,%2,%3};\n"
        : "+f"(c[0]), "+f"(c[1]), "+f"(c[2]), "+f"(c[3])
        : "r"(a[0]), "r"(a[1]), "r"(a[2]), "r"(a[3]), "r"(b0), "r"(b1));
}
__device__ __forceinline__ uint32_t f22h(float a, float b) {
    __half2 h = __floats2half2_rn(a, b);
    return *(uint32_t*)&h;
}

// ---------------------------------------------------------------------------
// Embedding + sinusoidal positional encoding (writes f32 + half copies)
// ---------------------------------------------------------------------------
__global__ void embed_kernel(const int* __restrict__ x,
                             const float* __restrict__ emb,
                             float* __restrict__ out,
                             __half* __restrict__ outh)
{
    int row = blockIdx.x;
    int s   = row & (S_LEN - 1);
    int tok = x[row];
    const float* erow = emb + (size_t)tok * E_DIM;
    float* orow = out + (size_t)row * E_DIM;
    __half* ohrow = outh + (size_t)row * E_DIM;

    int e0 = threadIdx.x * 4;
    #pragma unroll
    for (int j = 0; j < 4; j++) {
        int e = e0 + j;
        int even = e & ~1;
        float expo = (float)even / (float)E_DIM;
        float denom = powf(10000.0f, expo);
        float ang = (float)s / denom;
        float pe = (e & 1) ? cosf(ang) : sinf(ang);
        float v = erow[e] + pe;
        orow[e] = v;
        ohrow[e] = __float2half_rn(v);
    }
}

// ---------------------------------------------------------------------------
// Batched transpose+half, 64x64 tiles, swizzled SMEM, float4 loads.
// Dz[n][k] = half(Wz[k][n]); block (16,16); grid (N/64, K/64, L)
// ---------------------------------------------------------------------------
__global__ __launch_bounds__(256)
void transpose_half_b4(const float* __restrict__ W, __half* __restrict__ dst,
                       int Kd, int Nd, size_t src_stride, size_t dst_stride)
{
    __shared__ float tile[64][64];
    const float* Wz = W + (size_t)blockIdx.z * src_stride;
    __half* Dz = dst + (size_t)blockIdx.z * dst_stride;
    int n0 = blockIdx.x * 64, k0 = blockIdx.y * 64;
    int tx = threadIdx.x, ty = threadIdx.y;   // 16 x 16

    #pragma unroll
    for (int i = 0; i < 4; i++) {
        int r = ty + 16 * i;
        float4 v = *(const float4*)(Wz + (size_t)(k0 + r) * Nd + n0 + 4 * tx);
        tile[r][(4 * tx     + r) & 63] = v.x;
        tile[r][(4 * tx + 1 + r) & 63] = v.y;
        tile[r][(4 * tx + 2 + r) & 63] = v.z;
        tile[r][(4 * tx + 3 + r) & 63] = v.w;
    }
    __syncthreads();
    #pragma unroll
    for (int i = 0; i < 4; i++) {
        int nr = ty + 16 * i;
        float a0 = tile[4 * tx    ][(nr + 4 * tx)     & 63];
        float a1 = tile[4 * tx + 1][(nr + 4 * tx + 1) & 63];
        float a2 = tile[4 * tx + 2][(nr + 4 * tx + 2) & 63];
        float a3 = tile[4 * tx + 3][(nr + 4 * tx + 3) & 63];
        uint2 u;
        u.x = f22h(a0, a1);
        u.y = f22h(a2, a3);
        *(uint2*)(Dz + (size_t)(n0 + nr) * Kd + k0 + 4 * tx) = u;
    }
}

__global__ void pack_qkv_bias(const float* __restrict__ bq,
                              const float* __restrict__ bk,
                              const float* __restrict__ bv,
                              float* __restrict__ out)
{
    int i = blockIdx.x * 256 + threadIdx.x;
    int layer = i / QKV_STR, c = i % QKV_STR;
    float v;
    if (c < E_DIM)           v = bq[layer * E_DIM + c];
    else if (c < 2 * E_DIM)  v = bk[layer * E_DIM + c - E_DIM];
    else                     v = bv[layer * E_DIM + c - 2 * E_DIM];
    out[i] = v;
}

// ---------------------------------------------------------------------------
// FP16 GEMM: CTA 128x128, warp 64x32, BK=32, ROWB=112, 3-stage cp.async,
// 2 CTAs/SM. Grid: x = M tiles (fastest) -> B panel L2 reuse across wave.
// ---------------------------------------------------------------------------
#define GBM 128
#define GBN 128
#define GBK 32
#define ROWB 112
#define OP_ST (128 * ROWB)
#define STG   (2 * OP_ST)
#define NST   3
#define GEMM_SMEM (NST * STG)

template<int RELU, int WF, int WH, int ADDR>
__global__ __launch_bounds__(256, 2)
void hgemm5(const __half* __restrict__ A, const __half* __restrict__ Bt,
            const float* __restrict__ bias, const float* __restrict__ Rf,
            float* __restrict__ Cf, __half* __restrict__ Ch,
            int Nd, int Kd)
{
    extern __shared__ char smem[];
    const uint32_t sbase = smem_u32(smem);

    const int tid  = threadIdx.x;
    const int lane = tid & 31;
    const int wid  = tid >> 5;
    const int gid  = lane >> 2;
    const int tig  = lane & 3;

    const int m0 = blockIdx.x * GBM;     // M fastest
    const int n0 = blockIdx.y * GBN;
    const int wm = (wid >> 2) * 64;
    const int wn = (wid & 3) * 32;

    const int arow   = wm + (lane & 15);
    const int akoh   = (lane & 16) ? 8 : 0;
    const int brow16 = wn + (lane & 7) + ((lane & 16) ? 8 : 0);
    const int bkoh   = (lane & 8) ? 8 : 0;

    const int s_row = tid >> 2;
    const int s_q   = tid & 3;

    float acc[4][4][4];
    #pragma unroll
    for (int i = 0; i < 4; i++)
        #pragma unroll
        for (int j = 0; j < 4; j++)
            #pragma unroll
            for (int r = 0; r < 4; r++) acc[i][j][r] = 0.0f;

    const int nK = Kd / GBK;

    auto issue_stage = [&](int t, int buf) {
        const uint32_t base = sbase + buf * STG;
        const __half* Ag = A + (size_t)m0 * Kd + t * GBK;
        const __half* Bg = Bt + (size_t)n0 * Kd + t * GBK;
        #pragma unroll
        for (int p = 0; p < 2; p++) {
            int r = s_row + p * 64;
            uint32_t da = base + r * ROWB + s_q * 16;
            const __half* sa = Ag + (size_t)r * Kd + s_q * 8;
            asm volatile("cp.async.cg.shared.global [%0], [%1], 16;\n"
                         :: "r"(da), "l"(sa));
            uint32_t db = base + OP_ST + r * ROWB + s_q * 16;
            const __half* sb = Bg + (size_t)r * Kd + s_q * 8;
            asm volatile("cp.async.cg.shared.global [%0], [%1], 16;\n"
                         :: "r"(db), "l"(sb));
        }
        asm volatile("cp.async.commit_group;\n");
    };

    issue_stage(0, 0);
    if (nK > 1) issue_stage(1, 1);

    int buf = 0;
    for (int t = 0; t < nK; t++) {
        if (t + 1 < nK) asm volatile("cp.async.wait_group 1;\n");
        else            asm volatile("cp.async.wait_group 0;\n");
        __syncthreads();

        if (t + 2 < nK) {
            int nb = buf + 2; if (nb >= NST) nb -= NST;
            issue_stage(t + 2, nb);
        }

        const uint32_t sA = sbase + buf * STG;
        const uint32_t sB = sA + OP_ST;
        #pragma unroll
        for (int ko = 0; ko < GBK; ko += 16) {
            uint32_t af[4][4], bf[4][2];
            #pragma unroll
            for (int mt = 0; mt < 4; mt++)
                ldsm_x4(af[mt], sA + (arow + mt * 16) * ROWB + (ko + akoh) * 2);
            #pragma unroll
            for (int g = 0; g < 2; g++) {
                uint32_t r[4];
                ldsm_x4(r, sB + (brow16 + g * 16) * ROWB + (ko + bkoh) * 2);
                bf[2 * g][0] = r[0]; bf[2 * g][1] = r[1];
                bf[2 * g + 1][0] = r[2]; bf[2 * g + 1][1] = r[3];
            }
            #pragma unroll
            for (int mt = 0; mt < 4; mt++)
                #pragma unroll
                for (int nt = 0; nt < 4; nt++)
                    mma16816(acc[mt][nt], af[mt], bf[nt][0], bf[nt][1]);
        }
        if (++buf >= NST) buf = 0;
    }

    #pragma unroll
    for (int nt = 0; nt < 4; nt++) {
        int col = n0 + wn + nt * 8 + 2 * tig;
        float b0 = bias[col];
        float b1 = bias[col + 1];
        #pragma unroll
        for (int mt = 0; mt < 4; mt++) {
            int row = m0 + wm + mt * 16 + gid;
            float v00 = acc[mt][nt][0] + b0;
            float v01 = acc[mt][nt][1] + b1;
            float v10 = acc[mt][nt][2] + b0;
            float v11 = acc[mt][nt][3] + b1;
            if (ADDR) {
                float2 r0 = *(const float2*)(Rf + (size_t)row * Nd + col);
                float2 r1 = *(const float2*)(Rf + (size_t)(row + 8) * Nd + col);
                v00 += r0.x; v01 += r0.y;
                v10 += r1.x; v11 += r1.y;
            }
            if (RELU) {
                v00 = fmaxf(v00, 0.0f); v01 = fmaxf(v01, 0.0f);
                v10 = fmaxf(v10, 0.0f); v11 = fmaxf(v11, 0.0f);
            }
            if (WF) {
                float2 f0 = {v00, v01}, f1 = {v10, v11};
                *(float2*)(Cf + (size_t)row * Nd + col)       = f0;
                *(float2*)(Cf + (size_t)(row + 8) * Nd + col) = f1;
            }
            if (WH) {
                __half2 h0 = __floats2half2_rn(v00, v01);
                __half2 h1 = __floats2half2_rn(v10, v11);
                *(__half2*)(Ch + (size_t)row * Nd + col)       = h0;
                *(__half2*)(Ch + (size_t)(row + 8) * Nd + col) = h1;
            }
        }
    }
}

// ---------------------------------------------------------------------------
// FP16 flash attention (round-12, unchanged)
// ---------------------------------------------------------------------------
#define AROWB 144
#define AOP   (128 * AROWB)
#define ATTN_SMEM (5 * AOP)

__global__ __launch_bounds__(256)
void flash_attn_h(const __half* __restrict__ QKV, __half* __restrict__ O)
{
    extern __shared__ char smem[];
    const uint32_t sbase = smem_u32(smem);
    const uint32_t sQ = sbase;

    const int tid  = threadIdx.x;
    const int lane = tid & 31;
    const int wid  = tid >> 5;
    const int gid  = lane >> 2;
    const int tig  = lane & 3;

    const int qt = gridDim.x - 1 - blockIdx.x;
    const int h  = blockIdx.y;
    const int n  = blockIdx.z;
    const size_t rowbase = (size_t)n * S_LEN;
    const int hq = h * D_DIM;
    const int hk = E_DIM + h * D_DIM;
    const int hv = 2 * E_DIM + h * D_DIM;
    const size_t bout = rowbase * E_DIM + h * D_DIM;
    const float scale = 1.0f / 32.0f;
    const int wrow = wid * 16;
    const int rbase = wrow + gid;

    const int s_r = tid >> 2;
    const int s_q = tid & 3;

    #pragma unroll
    for (int p = 0; p < 2; p++) {
        int r = s_r + p * 64;
        const __half* src = QKV + (rowbase + qt * 128 + r) * QKV_STR + hq;
        #pragma unroll
        for (int j = 0; j < 2; j++) {
            int q = s_q + j * 4;
            asm volatile("cp.async.cg.shared.global [%0], [%1], 16;\n"
                         :: "r"(sQ + r * AROWB + q * 16), "l"(src + q * 8));
        }
    }

    auto stage_kv = [&](int kt, int b) {
        const uint32_t sK = sbase + AOP + b * AOP;
        const uint32_t sV = sbase + 3 * AOP + b * AOP;
        #pragma unroll
        for (int p = 0; p < 2; p++) {
            int r = s_r + p * 64;
            const __half* srck = QKV + (rowbase + kt * 128 + r) * QKV_STR + hk;
            const __half* srcv = QKV + (rowbase + kt * 128 + r) * QKV_STR + hv;
            #pragma unroll
            for (int j = 0; j < 2; j++) {
                int q = s_q + j * 4;
                asm volatile("cp.async.cg.shared.global [%0], [%1], 16;\n"
                             :: "r"(sK + r * AROWB + q * 16), "l"(srck + q * 8));
                asm volatile("cp.async.cg.shared.global [%0], [%1], 16;\n"
                             :: "r"(sV + r * AROWB + q * 16), "l"(srcv + q * 8));
            }
        }
    };

    stage_kv(0, 0);
    asm volatile("cp.async.commit_group;\n");

    float accO[8][4];
    #pragma unroll
    for (int i = 0; i < 8; i++)
        #pragma unroll
        for (int j = 0; j < 4; j++) accO[i][j] = 0.0f;
    float m0 = -1e30f, m1 = -1e30f, l0 = 0.0f, l1 = 0.0f;

    int buf = 0;
    for (int kt = 0; kt <= qt; kt++) {
        asm volatile("cp.async.wait_group 0;\n");
        __syncthreads();
        if (kt < qt) {
            stage_kv(kt + 1, buf ^ 1);
            asm volatile("cp.async.commit_group;\n");
        }
        const uint32_t sK = sbase + AOP + buf * AOP;
        const uint32_t sV = sbase + 3 * AOP + buf * AOP;

        float accS[16][4];
        #pragma unroll
        for (int i = 0; i < 16; i++)
            #pragma unroll
            for (int j = 0; j < 4; j++) accS[i][j] = 0.0f;

        #pragma unroll
        for (int ko = 0; ko < 64; ko += 16) {
            uint32_t af[4];
            ldsm_x4(af, sQ + (wrow + (lane & 15)) * AROWB
                        + (ko + ((lane & 16) ? 8 : 0)) * 2);
            #pragma unroll
            for (int g = 0; g < 8; g++) {
                uint32_t kr[4];
                ldsm_x4(kr, sK + (g * 16 + (lane & 7) + ((lane & 16) ? 8 : 0)) * AROWB
                            + (ko + ((lane & 8) ? 8 : 0)) * 2);
                mma16816(accS[2 * g],     af, kr[0], kr[1]);
                mma16816(accS[2 * g + 1], af, kr[2], kr[3]);
            }
        }

        #pragma unroll
        for (int i = 0; i < 16; i++)
            #pragma unroll
            for (int j = 0; j < 4; j++) accS[i][j] *= scale;

        if (kt == qt) {
            #pragma unroll
            for (int nt = 0; nt < 16; nt++) {
                int c = nt * 8 + 2 * tig;
                if (c     > rbase    ) accS[nt][0] = -1e30f;
                if (c + 1 > rbase    ) accS[nt][1] = -1e30f;
                if (c     > rbase + 8) accS[nt][2] = -1e30f;
                if (c + 1 > rbase + 8) accS[nt][3] = -1e30f;
            }
        }

        float mx0 = -1e30f, mx1 = -1e30f;
        #pragma unroll
        for (int nt = 0; nt < 16; nt++) {
            mx0 = fmaxf(mx0, fmaxf(accS[nt][0], accS[nt][1]));
            mx1 = fmaxf(mx1, fmaxf(accS[nt][2], accS[nt][3]));
        }
        mx0 = fmaxf(mx0, __shfl_xor_sync(0xffffffffu, mx0, 1));
        mx0 = fmaxf(mx0, __shfl_xor_sync(0xffffffffu, mx0, 2));
        mx1 = fmaxf(mx1, __shfl_xor_sync(0xffffffffu, mx1, 1));
        mx1 = fmaxf(mx1, __shfl_xor_sync(0xffffffffu, mx1, 2));

        float mn0 = fmaxf(m0, mx0), mn1 = fmaxf(m1, mx1);
        float al0 = __expf(m0 - mn0), al1 = __expf(m1 - mn1);
        m0 = mn0; m1 = mn1;

        float s0 = 0.0f, s1 = 0.0f;
        #pragma unroll
        for (int nt = 0; nt < 16; nt++) {
            float p0 = __expf(accS[nt][0] - mn0);
            float p1 = __expf(accS[nt][1] - mn0);
            float p2 = __expf(accS[nt][2] - mn1);
            float p3 = __expf(accS[nt][3] - mn1);
            accS[nt][0] = p0; accS[nt][1] = p1;
            accS[nt][2] = p2; accS[nt][3] = p3;
            s0 += p0 + p1; s1 += p2 + p3;
        }
        s0 += __shfl_xor_sync(0xffffffffu, s0, 1);
        s0 += __shfl_xor_sync(0xffffffffu, s0, 2);
        s1 += __shfl_xor_sync(0xffffffffu, s1, 1);
        s1 += __shfl_xor_sync(0xffffffffu, s1, 2);
        l0 = l0 * al0 + s0;
        l1 = l1 * al1 + s1;

        #pragma unroll
        for (int i = 0; i < 8; i++) {
            accO[i][0] *= al0; accO[i][1] *= al0;
            accO[i][2] *= al1; accO[i][3] *= al1;
        }

        #pragma unroll
        for (int ki = 0; ki < 8; ki++) {
            uint32_t pa[4];
            pa[0] = f22h(accS[2 * ki][0],     accS[2 * ki][1]);
            pa[1] = f22h(accS[2 * ki][2],     accS[2 * ki][3]);
            pa[2] = f22h(accS[2 * ki + 1][0], accS[2 * ki + 1][1]);
            pa[3] = f22h(accS[2 * ki + 1][2], accS[2 * ki + 1][3]);
            #pragma unroll
            for (int dt = 0; dt < 4; dt++) {
                uint32_t vr[4];
                ldsm_x4t(vr, sV + (ki * 16 + (lane & 7) + ((lane & 8) ? 8 : 0)) * AROWB
                             + (dt * 16 + ((lane & 16) ? 8 : 0)) * 2);
                mma16816(accO[2 * dt],     pa, vr[0], vr[1]);
                mma16816(accO[2 * dt + 1], pa, vr[2], vr[3]);
            }
        }
        __syncthreads();
        buf ^= 1;
    }

    float inv0 = 1.0f / l0, inv1 = 1.0f / l1;
    #pragma unroll
    for (int nt = 0; nt < 8; nt++) {
        int col = nt * 8 + 2 * tig;
        __half2 o0 = __floats2half2_rn(accO[nt][0] * inv0, accO[nt][1] * inv0);
        __half2 o1 = __floats2half2_rn(accO[nt][2] * inv1, accO[nt][3] * inv1);
        *(__half2*)(O + bout + (size_t)(qt * 128 + rbase    ) * E_DIM + col) = o0;
        *(__half2*)(O + bout + (size_t)(qt * 128 + rbase + 8) * E_DIM + col) = o1;
    }
}

// ---------------------------------------------------------------------------
// LayerNorm, warp-per-row (8 rows/CTA), shfl-only reductions.
// Writes f32 + half copies.
// ---------------------------------------------------------------------------
__global__ __launch_bounds__(256)
void ln_kernel(const float* __restrict__ xin,
               const float* __restrict__ g, const float* __restrict__ beta,
               float* __restrict__ out, __half* __restrict__ outh)
{
    const int warp = threadIdx.x >> 5;
    const int lane = threadIdx.x & 31;
    const int row = blockIdx.x * 8 + warp;
    const float* xr = xin + (size_t)row * E_DIM;
    float* orow = out + (size_t)row * E_DIM;
    __half* ohrow = outh + (size_t)row * E_DIM;

    float4 xv[8];
    float lsum = 0.0f;
    #pragma unroll
    for (int j = 0; j < 8; j++) {
        xv[j] = *(const float4*)(xr + lane * 4 + j * 128);
        lsum += (xv[j].x + xv[j].y) + (xv[j].z + xv[j].w);
    }
    #pragma unroll
    for (int s = 16; s > 0; s >>= 1)
        lsum += __shfl_xor_sync(0xffffffffu, lsum, s);
    float mean = lsum * (1.0f / E_DIM);

    float lvar = 0.0f;
    #pragma unroll
    for (int j = 0; j < 8; j++) {
        float d0 = xv[j].x - mean, d1 = xv[j].y - mean;
        float d2 = xv[j].z - mean, d3 = xv[j].w - mean;
        lvar += (d0 * d0 + d1 * d1) + (d2 * d2 + d3 * d3);
    }
    #pragma unroll
    for (int s = 16; s > 0; s >>= 1)
        lvar += __shfl_xor_sync(0xffffffffu, lvar, s);
    float rstd = rsqrtf(lvar * (1.0f / E_DIM) + 1e-5f);

    #pragma unroll
    for (int j = 0; j < 8; j++) {
        int e = lane * 4 + j * 128;
        float4 gv = *(const float4*)(g + e);
        float4 bv = *(const float4*)(beta + e);
        float4 o;
        o.x = (xv[j].x - mean) * rstd * gv.x + bv.x;
        o.y = (xv[j].y - mean) * rstd * gv.y + bv.y;
        o.z = (xv[j].z - mean) * rstd * gv.z + bv.z;
        o.w = (xv[j].w - mean) * rstd * gv.w + bv.w;
        *(float4*)(orow + e) = o;
        uint2 u;
        u.x = f22h(o.x, o.y);
        u.y = f22h(o.z, o.w);
        *(uint2*)(ohrow + e) = u;
    }
}

// ---------------------------------------------------------------------------
// Launch
// ---------------------------------------------------------------------------
extern "C" void kernel_launch(void* const* d_in, const int* in_sizes, int n_in,
                              void* d_out, int out_size)
{
    const int*   x    = (const int*)  d_in[0];
    const float* emb  = (const float*)d_in[1];
    const float* Wq   = (const float*)d_in[2];
    const float* bq   = (const float*)d_in[3];
    const float* Wk   = (const float*)d_in[4];
    const float* bk   = (const float*)d_in[5];
    const float* Wv   = (const float*)d_in[6];
    const float* bv   = (const float*)d_in[7];
    const float* Wo   = (const float*)d_in[8];
    const float* bo   = (const float*)d_in[9];
    const float* ln1g = (const float*)d_in[10];
    const float* ln1b = (const float*)d_in[11];
    const float* ln2g = (const float*)d_in[12];
    const float* ln2b = (const float*)d_in[13];
    const float* W1   = (const float*)d_in[14];
    const float* b1   = (const float*)d_in[15];
    const float* W2   = (const float*)d_in[16];
    const float* b2   = (const float*)d_in[17];
    const float* Wout = (const float*)d_in[18];
    const float* bout = (const float*)d_in[19];
    float* out = (float*)d_out;

    float *act, *tmp, *hbuf, *bqkv;
    __half *act_h, *qkv_h, *attn_h, *h_h, *ff_h, *wh;
    cudaGetSymbolAddress((void**)&act,    g_act);
    cudaGetSymbolAddress((void**)&act_h,  g_act_h);
    cudaGetSymbolAddress((void**)&qkv_h,  g_qkv_h);
    cudaGetSymbolAddress((void**)&attn_h, g_attn_h);
    cudaGetSymbolAddress((void**)&tmp,    g_tmp);
    cudaGetSymbolAddress((void**)&hbuf,   g_h);
    cudaGetSymbolAddress((void**)&h_h,    g_h_h);
    cudaGetSymbolAddress((void**)&ff_h,   g_ff_h);
    cudaGetSymbolAddress((void**)&bqkv,   g_bqkv);
    cudaGetSymbolAddress((void**)&wh,     g_wh);

    static int attr_set = 0;
    if (!attr_set) {
        cudaFuncSetAttribute(flash_attn_h,
                             cudaFuncAttributeMaxDynamicSharedMemorySize, ATTN_SMEM);
        cudaFuncSetAttribute(hgemm5<0, 0, 1, 0>,
                             cudaFuncAttributeMaxDynamicSharedMemorySize, GEMM_SMEM);
        cudaFuncSetAttribute(hgemm5<1, 0, 1, 0>,
                             cudaFuncAttributeMaxDynamicSharedMemorySize, GEMM_SMEM);
        cudaFuncSetAttribute(hgemm5<0, 1, 0, 1>,
                             cudaFuncAttributeMaxDynamicSharedMemorySize, GEMM_SMEM);
        cudaFuncSetAttribute(hgemm5<0, 1, 0, 0>,
                             cudaFuncAttributeMaxDynamicSharedMemorySize, GEMM_SMEM);
        attr_set = 1;
    }

    // ---- upfront: weight transposes (batched, swizzled, float4) + bias pack
    {
        dim3 blk(16, 16);
        dim3 gEE(E_DIM / 64, E_DIM / 64, L_NUM);
        transpose_half_b4<<<gEE, blk>>>(Wq, wh + 0 * WO_LSTR, E_DIM, E_DIM,
                                        (size_t)E_DIM * E_DIM, QKV_LSTR);
        transpose_half_b4<<<gEE, blk>>>(Wk, wh + 1 * WO_LSTR, E_DIM, E_DIM,
                                        (size_t)E_DIM * E_DIM, QKV_LSTR);
        transpose_half_b4<<<gEE, blk>>>(Wv, wh + 2 * WO_LSTR, E_DIM, E_DIM,
                                        (size_t)E_DIM * E_DIM, QKV_LSTR);
        transpose_half_b4<<<gEE, blk>>>(Wo, wh + OFF_WO, E_DIM, E_DIM,
                                        (size_t)E_DIM * E_DIM, WO_LSTR);
        dim3 gW1(FF_DIM / 64, E_DIM / 64, L_NUM);
        transpose_half_b4<<<gW1, blk>>>(W1, wh + OFF_W1, E_DIM, FF_DIM,
                                        (size_t)E_DIM * FF_DIM, W1_LSTR);
        dim3 gW2(E_DIM / 64, FF_DIM / 64, L_NUM);
        transpose_half_b4<<<gW2, blk>>>(W2, wh + OFF_W2, FF_DIM, E_DIM,
                                        (size_t)FF_DIM * E_DIM, W2_LSTR);
        dim3 gWV(V_DIM / 64, E_DIM / 64, 1);
        transpose_half_b4<<<gWV, blk>>>(Wout, wh + OFF_WOUT, E_DIM, V_DIM,
                                        (size_t)E_DIM * V_DIM, 0);
        pack_qkv_bias<<<(L_NUM * QKV_STR) / 256, 256>>>(bq, bk, bv, bqkv);
    }

    embed_kernel<<<M_TOK, 256>>>(x, emb, act, act_h);

    for (int i = 0; i < L_NUM; i++) {
        size_t bo_off = (size_t)i * E_DIM;

        // QKV projection: half out
        hgemm5<0, 0, 1, 0><<<dim3(M_TOK / GBM, QKV_STR / GBN), 256, GEMM_SMEM>>>(
            act_h, wh + (size_t)i * QKV_LSTR, bqkv + (size_t)i * QKV_STR,
            (const float*)0, (float*)0, qkv_h, QKV_STR, E_DIM);

        flash_attn_h<<<dim3(S_LEN / 128, H_DIM, N_B), 256, ATTN_SMEM>>>(qkv_h, attn_h);

        // Wo GEMM + fused residual (act): x1 -> tmp (f32)
        hgemm5<0, 1, 0, 1><<<dim3(M_TOK / GBM, E_DIM / GBN), 256, GEMM_SMEM>>>(
            attn_h, wh + OFF_WO + (size_t)i * WO_LSTR, bo + bo_off,
            act, tmp, (__half*)0, E_DIM, E_DIM);

        ln_kernel<<<M_TOK / 8, 256>>>(tmp, ln1g + bo_off, ln1b + bo_off, hbuf, h_h);

        // FF1: half out (ReLU)
        hgemm5<1, 0, 1, 0><<<dim3(M_TOK / GBM, FF_DIM / GBN), 256, GEMM_SMEM>>>(
            h_h, wh + OFF_W1 + (size_t)i * W1_LSTR, b1 + (size_t)i * FF_DIM,
            (const float*)0, (float*)0, ff_h, FF_DIM, E_DIM);

        // FF2 + fused residual (hbuf): x2 -> tmp (f32)
        hgemm5<0, 1, 0, 1><<<dim3(M_TOK / GBM, E_DIM / GBN), 256, GEMM_SMEM>>>(
            ff_h, wh + OFF_W2 + (size_t)i * W2_LSTR, b2 + bo_off,
            hbuf, tmp, (__half*)0, E_DIM, FF_DIM);

        ln_kernel<<<M_TOK / 8, 256>>>(tmp, ln2g + bo_off, ln2b + bo_off, act, act_h);
    }

    hgemm5<0, 1, 0, 0><<<dim3(M_TOK / GBM, V_DIM / GBN), 256, GEMM_SMEM>>>(
        act_h, wh + OFF_WOUT, bout, (const float*)0, out, (__half*)0, V_DIM, E_DIM);
}

// round 15
// speedup vs baseline: 1.3640x; 1.0015x over previous
#include <cuda_runtime.h>
#include <cuda_fp16.h>
#include <math.h>
#include <stdint.h>

#define E_DIM 1024
#define H_DIM 16
#define D_DIM 64
#define S_LEN 1024
#define N_B   4
#define L_NUM 4
#define FF_DIM 4096
#define V_DIM 32000
#define M_TOK (N_B * S_LEN)   // 4096 token rows
#define QKV_STR (3 * E_DIM)   // 3072

// ---------------------------------------------------------------------------
// Transposed-weight half buffer layout (element offsets)
// ---------------------------------------------------------------------------
#define QKV_LSTR   (3 * E_DIM * E_DIM)
#define OFF_WO     (L_NUM * QKV_LSTR)
#define WO_LSTR    (E_DIM * E_DIM)
#define OFF_W1     (OFF_WO + L_NUM * WO_LSTR)
#define W1_LSTR    (E_DIM * FF_DIM)
#define OFF_W2     (OFF_W1 + L_NUM * W1_LSTR)
#define W2_LSTR    (FF_DIM * E_DIM)
#define OFF_WOUT   (OFF_W2 + L_NUM * W2_LSTR)
#define WH_TOTAL   (OFF_WOUT + (size_t)V_DIM * E_DIM)

// ---------------------------------------------------------------------------
// Scratch (device globals; no allocations allowed)
// ---------------------------------------------------------------------------
__device__ float  g_act  [M_TOK * E_DIM];
__device__ __half g_act_h[M_TOK * E_DIM];
__device__ __half g_qkv_h[M_TOK * QKV_STR];
__device__ __half g_attn_h[M_TOK * E_DIM];
__device__ float  g_tmp  [M_TOK * E_DIM];
__device__ float  g_h    [M_TOK * E_DIM];
__device__ __half g_h_h  [M_TOK * E_DIM];
__device__ __half g_ff_h [M_TOK * FF_DIM];
__device__ float  g_bqkv [L_NUM * QKV_STR];
__device__ __half g_wh   [WH_TOTAL];

__device__ __forceinline__ uint32_t smem_u32(const void* p) {
    uint32_t a;
    asm("{ .reg .u64 t; cvta.to.shared.u64 t, %1; cvt.u32.u64 %0, t; }"
        : "=r"(a) : "l"(p));
    return a;
}

__device__ __forceinline__ void ldsm_x4(uint32_t* r, uint32_t addr) {
    asm volatile("ldmatrix.sync.aligned.m8n8.x4.shared.b16 {%0,%1,%2,%3}, [%4];"
                 : "=r"(r[0]), "=r"(r[1]), "=r"(r[2]), "=r"(r[3]) : "r"(addr));
}
__device__ __forceinline__ void ldsm_x4t(uint32_t* r, uint32_t addr) {
    asm volatile("ldmatrix.sync.aligned.m8n8.x4.trans.shared.b16 {%0,%1,%2,%3}, [%4];"
                 : "=r"(r[0]), "=r"(r[1]), "=r"(r[2]), "=r"(r[3]) : "r"(addr));
}
__device__ __forceinline__ void mma16816(float* c, const uint32_t* a,
                                         uint32_t b0, uint32_t b1) {
    asm volatile(
        "mma.sync.aligned.m16n8k16.row.col.f32.f16.f16.f32 "
        "{%0,%1,%2,%3}, {%4,%5,%6,%7}, {%8,%9}, {%0,%1,%2,%3};\n"
        : "+f"(c[0]), "+f"(c[1]), "+f"(c[2]), "+f"(c[3])
        : "r"(a[0]), "r"(a[1]), "r"(a[2]), "r"(a[3]), "r"(b0), "r"(b1));
}
__device__ __forceinline__ uint32_t f22h(float a, float b) {
    __half2 h = __floats2half2_rn(a, b);
    return *(uint32_t*)&h;
}

// ---------------------------------------------------------------------------
// Embedding + sinusoidal positional encoding (writes f32 + half copies)
// ---------------------------------------------------------------------------
__global__ void embed_kernel(const int* __restrict__ x,
                             const float* __restrict__ emb,
                             float* __restrict__ out,
                             __half* __restrict__ outh)
{
    int row = blockIdx.x;
    int s   = row & (S_LEN - 1);
    int tok = x[row];
    const float* erow = emb + (size_t)tok * E_DIM;
    float* orow = out + (size_t)row * E_DIM;
    __half* ohrow = outh + (size_t)row * E_DIM;

    int e0 = threadIdx.x * 4;
    #pragma unroll
    for (int j = 0; j < 4; j++) {
        int e = e0 + j;
        int even = e & ~1;
        float expo = (float)even / (float)E_DIM;
        float denom = powf(10000.0f, expo);
        float ang = (float)s / denom;
        float pe = (e & 1) ? cosf(ang) : sinf(ang);
        float v = erow[e] + pe;
        orow[e] = v;
        ohrow[e] = __float2half_rn(v);
    }
}

// ---------------------------------------------------------------------------
// Batched transpose+half, 64x64 tiles, swizzled SMEM, float4 loads.
// ---------------------------------------------------------------------------
__global__ __launch_bounds__(256)
void transpose_half_b4(const float* __restrict__ W, __half* __restrict__ dst,
                       int Kd, int Nd, size_t src_stride, size_t dst_stride)
{
    __shared__ float tile[64][64];
    const float* Wz = W + (size_t)blockIdx.z * src_stride;
    __half* Dz = dst + (size_t)blockIdx.z * dst_stride;
    int n0 = blockIdx.x * 64, k0 = blockIdx.y * 64;
    int tx = threadIdx.x, ty = threadIdx.y;   // 16 x 16

    #pragma unroll
    for (int i = 0; i < 4; i++) {
        int r = ty + 16 * i;
        float4 v = *(const float4*)(Wz + (size_t)(k0 + r) * Nd + n0 + 4 * tx);
        tile[r][(4 * tx     + r) & 63] = v.x;
        tile[r][(4 * tx + 1 + r) & 63] = v.y;
        tile[r][(4 * tx + 2 + r) & 63] = v.z;
        tile[r][(4 * tx + 3 + r) & 63] = v.w;
    }
    __syncthreads();
    #pragma unroll
    for (int i = 0; i < 4; i++) {
        int nr = ty + 16 * i;
        float a0 = tile[4 * tx    ][(nr + 4 * tx)     & 63];
        float a1 = tile[4 * tx + 1][(nr + 4 * tx + 1) & 63];
        float a2 = tile[4 * tx + 2][(nr + 4 * tx + 2) & 63];
        float a3 = tile[4 * tx + 3][(nr + 4 * tx + 3) & 63];
        uint2 u;
        u.x = f22h(a0, a1);
        u.y = f22h(a2, a3);
        *(uint2*)(Dz + (size_t)(n0 + nr) * Kd + k0 + 4 * tx) = u;
    }
}

__global__ void pack_qkv_bias(const float* __restrict__ bq,
                              const float* __restrict__ bk,
                              const float* __restrict__ bv,
                              float* __restrict__ out)
{
    int i = blockIdx.x * 256 + threadIdx.x;
    int layer = i / QKV_STR, c = i % QKV_STR;
    float v;
    if (c < E_DIM)           v = bq[layer * E_DIM + c];
    else if (c < 2 * E_DIM)  v = bk[layer * E_DIM + c - E_DIM];
    else                     v = bv[layer * E_DIM + c - 2 * E_DIM];
    out[i] = v;
}

// ---------------------------------------------------------------------------
// FP16 GEMM: CTA 128x128, warp 64x32, BK=32, ROWB=112, 3-stage cp.async,
// 2 CTAs/SM. Grid: x = M tiles (fastest).
// ---------------------------------------------------------------------------
#define GBM 128
#define GBN 128
#define GBK 32
#define ROWB 112
#define OP_ST (128 * ROWB)
#define STG   (2 * OP_ST)
#define NST   3
#define GEMM_SMEM (NST * STG)

template<int RELU, int WF, int WH, int ADDR>
__global__ __launch_bounds__(256, 2)
void hgemm5(const __half* __restrict__ A, const __half* __restrict__ Bt,
            const float* __restrict__ bias, const float* __restrict__ Rf,
            float* __restrict__ Cf, __half* __restrict__ Ch,
            int Nd, int Kd)
{
    extern __shared__ char smem[];
    const uint32_t sbase = smem_u32(smem);

    const int tid  = threadIdx.x;
    const int lane = tid & 31;
    const int wid  = tid >> 5;
    const int gid  = lane >> 2;
    const int tig  = lane & 3;

    const int m0 = blockIdx.x * GBM;
    const int n0 = blockIdx.y * GBN;
    const int wm = (wid >> 2) * 64;
    const int wn = (wid & 3) * 32;

    const int arow   = wm + (lane & 15);
    const int akoh   = (lane & 16) ? 8 : 0;
    const int brow16 = wn + (lane & 7) + ((lane & 16) ? 8 : 0);
    const int bkoh   = (lane & 8) ? 8 : 0;

    const int s_row = tid >> 2;
    const int s_q   = tid & 3;

    float acc[4][4][4];
    #pragma unroll
    for (int i = 0; i < 4; i++)
        #pragma unroll
        for (int j = 0; j < 4; j++)
            #pragma unroll
            for (int r = 0; r < 4; r++) acc[i][j][r] = 0.0f;

    const int nK = Kd / GBK;

    auto issue_stage = [&](int t, int buf) {
        const uint32_t base = sbase + buf * STG;
        const __half* Ag = A + (size_t)m0 * Kd + t * GBK;
        const __half* Bg = Bt + (size_t)n0 * Kd + t * GBK;
        #pragma unroll
        for (int p = 0; p < 2; p++) {
            int r = s_row + p * 64;
            uint32_t da = base + r * ROWB + s_q * 16;
            const __half* sa = Ag + (size_t)r * Kd + s_q * 8;
            asm volatile("cp.async.cg.shared.global [%0], [%1], 16;\n"
                         :: "r"(da), "l"(sa));
            uint32_t db = base + OP_ST + r * ROWB + s_q * 16;
            const __half* sb = Bg + (size_t)r * Kd + s_q * 8;
            asm volatile("cp.async.cg.shared.global [%0], [%1], 16;\n"
                         :: "r"(db), "l"(sb));
        }
        asm volatile("cp.async.commit_group;\n");
    };

    issue_stage(0, 0);
    if (nK > 1) issue_stage(1, 1);

    int buf = 0;
    for (int t = 0; t < nK; t++) {
        if (t + 1 < nK) asm volatile("cp.async.wait_group 1;\n");
        else            asm volatile("cp.async.wait_group 0;\n");
        __syncthreads();

        if (t + 2 < nK) {
            int nb = buf + 2; if (nb >= NST) nb -= NST;
            issue_stage(t + 2, nb);
        }

        const uint32_t sA = sbase + buf * STG;
        const uint32_t sB = sA + OP_ST;
        #pragma unroll
        for (int ko = 0; ko < GBK; ko += 16) {
            uint32_t af[4][4], bf[4][2];
            #pragma unroll
            for (int mt = 0; mt < 4; mt++)
                ldsm_x4(af[mt], sA + (arow + mt * 16) * ROWB + (ko + akoh) * 2);
            #pragma unroll
            for (int g = 0; g < 2; g++) {
                uint32_t r[4];
                ldsm_x4(r, sB + (brow16 + g * 16) * ROWB + (ko + bkoh) * 2);
                bf[2 * g][0] = r[0]; bf[2 * g][1] = r[1];
                bf[2 * g + 1][0] = r[2]; bf[2 * g + 1][1] = r[3];
            }
            #pragma unroll
            for (int mt = 0; mt < 4; mt++)
                #pragma unroll
                for (int nt = 0; nt < 4; nt++)
                    mma16816(acc[mt][nt], af[mt], bf[nt][0], bf[nt][1]);
        }
        if (++buf >= NST) buf = 0;
    }

    #pragma unroll
    for (int nt = 0; nt < 4; nt++) {
        int col = n0 + wn + nt * 8 + 2 * tig;
        float b0 = bias[col];
        float b1 = bias[col + 1];
        #pragma unroll
        for (int mt = 0; mt < 4; mt++) {
            int row = m0 + wm + mt * 16 + gid;
            float v00 = acc[mt][nt][0] + b0;
            float v01 = acc[mt][nt][1] + b1;
            float v10 = acc[mt][nt][2] + b0;
            float v11 = acc[mt][nt][3] + b1;
            if (ADDR) {
                float2 r0 = *(const float2*)(Rf + (size_t)row * Nd + col);
                float2 r1 = *(const float2*)(Rf + (size_t)(row + 8) * Nd + col);
                v00 += r0.x; v01 += r0.y;
                v10 += r1.x; v11 += r1.y;
            }
            if (RELU) {
                v00 = fmaxf(v00, 0.0f); v01 = fmaxf(v01, 0.0f);
                v10 = fmaxf(v10, 0.0f); v11 = fmaxf(v11, 0.0f);
            }
            if (WF) {
                float2 f0 = {v00, v01}, f1 = {v10, v11};
                *(float2*)(Cf + (size_t)row * Nd + col)       = f0;
                *(float2*)(Cf + (size_t)(row + 8) * Nd + col) = f1;
            }
            if (WH) {
                __half2 h0 = __floats2half2_rn(v00, v01);
                __half2 h1 = __floats2half2_rn(v10, v11);
                *(__half2*)(Ch + (size_t)row * Nd + col)       = h0;
                *(__half2*)(Ch + (size_t)(row + 8) * Nd + col) = h1;
            }
        }
    }
}

// ---------------------------------------------------------------------------
// FP16 flash attention (unchanged)
// ---------------------------------------------------------------------------
#define AROWB 144
#define AOP   (128 * AROWB)
#define ATTN_SMEM (5 * AOP)

__global__ __launch_bounds__(256)
void flash_attn_h(const __half* __restrict__ QKV, __half* __restrict__ O)
{
    extern __shared__ char smem[];
    const uint32_t sbase = smem_u32(smem);
    const uint32_t sQ = sbase;

    const int tid  = threadIdx.x;
    const int lane = tid & 31;
    const int wid  = tid >> 5;
    const int gid  = lane >> 2;
    const int tig  = lane & 3;

    const int qt = gridDim.x - 1 - blockIdx.x;
    const int h  = blockIdx.y;
    const int n  = blockIdx.z;
    const size_t rowbase = (size_t)n * S_LEN;
    const int hq = h * D_DIM;
    const int hk = E_DIM + h * D_DIM;
    const int hv = 2 * E_DIM + h * D_DIM;
    const size_t bout = rowbase * E_DIM + h * D_DIM;
    const float scale = 1.0f / 32.0f;
    const int wrow = wid * 16;
    const int rbase = wrow + gid;

    const int s_r = tid >> 2;
    const int s_q = tid & 3;

    #pragma unroll
    for (int p = 0; p < 2; p++) {
        int r = s_r + p * 64;
        const __half* src = QKV + (rowbase + qt * 128 + r) * QKV_STR + hq;
        #pragma unroll
        for (int j = 0; j < 2; j++) {
            int q = s_q + j * 4;
            asm volatile("cp.async.cg.shared.global [%0], [%1], 16;\n"
                         :: "r"(sQ + r * AROWB + q * 16), "l"(src + q * 8));
        }
    }

    auto stage_kv = [&](int kt, int b) {
        const uint32_t sK = sbase + AOP + b * AOP;
        const uint32_t sV = sbase + 3 * AOP + b * AOP;
        #pragma unroll
        for (int p = 0; p < 2; p++) {
            int r = s_r + p * 64;
            const __half* srck = QKV + (rowbase + kt * 128 + r) * QKV_STR + hk;
            const __half* srcv = QKV + (rowbase + kt * 128 + r) * QKV_STR + hv;
            #pragma unroll
            for (int j = 0; j < 2; j++) {
                int q = s_q + j * 4;
                asm volatile("cp.async.cg.shared.global [%0], [%1], 16;\n"
                             :: "r"(sK + r * AROWB + q * 16), "l"(srck + q * 8));
                asm volatile("cp.async.cg.shared.global [%0], [%1], 16;\n"
                             :: "r"(sV + r * AROWB + q * 16), "l"(srcv + q * 8));
            }
        }
    };

    stage_kv(0, 0);
    asm volatile("cp.async.commit_group;\n");

    float accO[8][4];
    #pragma unroll
    for (int i = 0; i < 8; i++)
        #pragma unroll
        for (int j = 0; j < 4; j++) accO[i][j] = 0.0f;
    float m0 = -1e30f, m1 = -1e30f, l0 = 0.0f, l1 = 0.0f;

    int buf = 0;
    for (int kt = 0; kt <= qt; kt++) {
        asm volatile("cp.async.wait_group 0;\n");
        __syncthreads();
        if (kt < qt) {
            stage_kv(kt + 1, buf ^ 1);
            asm volatile("cp.async.commit_group;\n");
        }
        const uint32_t sK = sbase + AOP + buf * AOP;
        const uint32_t sV = sbase + 3 * AOP + buf * AOP;

        float accS[16][4];
        #pragma unroll
        for (int i = 0; i < 16; i++)
            #pragma unroll
            for (int j = 0; j < 4; j++) accS[i][j] = 0.0f;

        #pragma unroll
        for (int ko = 0; ko < 64; ko += 16) {
            uint32_t af[4];
            ldsm_x4(af, sQ + (wrow + (lane & 15)) * AROWB
                        + (ko + ((lane & 16) ? 8 : 0)) * 2);
            #pragma unroll
            for (int g = 0; g < 8; g++) {
                uint32_t kr[4];
                ldsm_x4(kr, sK + (g * 16 + (lane & 7) + ((lane & 16) ? 8 : 0)) * AROWB
                            + (ko + ((lane & 8) ? 8 : 0)) * 2);
                mma16816(accS[2 * g],     af, kr[0], kr[1]);
                mma16816(accS[2 * g + 1], af, kr[2], kr[3]);
            }
        }

        #pragma unroll
        for (int i = 0; i < 16; i++)
            #pragma unroll
            for (int j = 0; j < 4; j++) accS[i][j] *= scale;

        if (kt == qt) {
            #pragma unroll
            for (int nt = 0; nt < 16; nt++) {
                int c = nt * 8 + 2 * tig;
                if (c     > rbase    ) accS[nt][0] = -1e30f;
                if (c + 1 > rbase    ) accS[nt][1] = -1e30f;
                if (c     > rbase + 8) accS[nt][2] = -1e30f;
                if (c + 1 > rbase + 8) accS[nt][3] = -1e30f;
            }
        }

        float mx0 = -1e30f, mx1 = -1e30f;
        #pragma unroll
        for (int nt = 0; nt < 16; nt++) {
            mx0 = fmaxf(mx0, fmaxf(accS[nt][0], accS[nt][1]));
            mx1 = fmaxf(mx1, fmaxf(accS[nt][2], accS[nt][3]));
        }
        mx0 = fmaxf(mx0, __shfl_xor_sync(0xffffffffu, mx0, 1));
        mx0 = fmaxf(mx0, __shfl_xor_sync(0xffffffffu, mx0, 2));
        mx1 = fmaxf(mx1, __shfl_xor_sync(0xffffffffu, mx1, 1));
        mx1 = fmaxf(mx1, __shfl_xor_sync(0xffffffffu, mx1, 2));

        float mn0 = fmaxf(m0, mx0), mn1 = fmaxf(m1, mx1);
        float al0 = __expf(m0 - mn0), al1 = __expf(m1 - mn1);
        m0 = mn0; m1 = mn1;

        float s0 = 0.0f, s1 = 0.0f;
        #pragma unroll
        for (int nt = 0; nt < 16; nt++) {
            float p0 = __expf(accS[nt][0] - mn0);
            float p1 = __expf(accS[nt][1] - mn0);
            float p2 = __expf(accS[nt][2] - mn1);
            float p3 = __expf(accS[nt][3] - mn1);
            accS[nt][0] = p0; accS[nt][1] = p1;
            accS[nt][2] = p2; accS[nt][3] = p3;
            s0 += p0 + p1; s1 += p2 + p3;
        }
        s0 += __shfl_xor_sync(0xffffffffu, s0, 1);
        s0 += __shfl_xor_sync(0xffffffffu, s0, 2);
        s1 += __shfl_xor_sync(0xffffffffu, s1, 1);
        s1 += __shfl_xor_sync(0xffffffffu, s1, 2);
        l0 = l0 * al0 + s0;
        l1 = l1 * al1 + s1;

        #pragma unroll
        for (int i = 0; i < 8; i++) {
            accO[i][0] *= al0; accO[i][1] *= al0;
            accO[i][2] *= al1; accO[i][3] *= al1;
        }

        #pragma unroll
        for (int ki = 0; ki < 8; ki++) {
            uint32_t pa[4];
            pa[0] = f22h(accS[2 * ki][0],     accS[2 * ki][1]);
            pa[1] = f22h(accS[2 * ki][2],     accS[2 * ki][3]);
            pa[2] = f22h(accS[2 * ki + 1][0], accS[2 * ki + 1][1]);
            pa[3] = f22h(accS[2 * ki + 1][2], accS[2 * ki + 1][3]);
            #pragma unroll
            for (int dt = 0; dt < 4; dt++) {
                uint32_t vr[4];
                ldsm_x4t(vr, sV + (ki * 16 + (lane & 7) + ((lane & 8) ? 8 : 0)) * AROWB
                             + (dt * 16 + ((lane & 16) ? 8 : 0)) * 2);
                mma16816(accO[2 * dt],     pa, vr[0], vr[1]);
                mma16816(accO[2 * dt + 1], pa, vr[2], vr[3]);
            }
        }
        __syncthreads();
        buf ^= 1;
    }

    float inv0 = 1.0f / l0, inv1 = 1.0f / l1;
    #pragma unroll
    for (int nt = 0; nt < 8; nt++) {
        int col = nt * 8 + 2 * tig;
        __half2 o0 = __floats2half2_rn(accO[nt][0] * inv0, accO[nt][1] * inv0);
        __half2 o1 = __floats2half2_rn(accO[nt][2] * inv1, accO[nt][3] * inv1);
        *(__half2*)(O + bout + (size_t)(qt * 128 + rbase    ) * E_DIM + col) = o0;
        *(__half2*)(O + bout + (size_t)(qt * 128 + rbase + 8) * E_DIM + col) = o1;
    }
}

// ---------------------------------------------------------------------------
// LayerNorm, warp-per-row (8 rows/CTA), shfl-only reductions.
// ---------------------------------------------------------------------------
__global__ __launch_bounds__(256)
void ln_kernel(const float* __restrict__ xin,
               const float* __restrict__ g, const float* __restrict__ beta,
               float* __restrict__ out, __half* __restrict__ outh)
{
    const int warp = threadIdx.x >> 5;
    const int lane = threadIdx.x & 31;
    const int row = blockIdx.x * 8 + warp;
    const float* xr = xin + (size_t)row * E_DIM;
    float* orow = out + (size_t)row * E_DIM;
    __half* ohrow = outh + (size_t)row * E_DIM;

    float4 xv[8];
    float lsum = 0.0f;
    #pragma unroll
    for (int j = 0; j < 8; j++) {
        xv[j] = *(const float4*)(xr + lane * 4 + j * 128);
        lsum += (xv[j].x + xv[j].y) + (xv[j].z + xv[j].w);
    }
    #pragma unroll
    for (int s = 16; s > 0; s >>= 1)
        lsum += __shfl_xor_sync(0xffffffffu, lsum, s);
    float mean = lsum * (1.0f / E_DIM);

    float lvar = 0.0f;
    #pragma unroll
    for (int j = 0; j < 8; j++) {
        float d0 = xv[j].x - mean, d1 = xv[j].y - mean;
        float d2 = xv[j].z - mean, d3 = xv[j].w - mean;
        lvar += (d0 * d0 + d1 * d1) + (d2 * d2 + d3 * d3);
    }
    #pragma unroll
    for (int s = 16; s > 0; s >>= 1)
        lvar += __shfl_xor_sync(0xffffffffu, lvar, s);
    float rstd = rsqrtf(lvar * (1.0f / E_DIM) + 1e-5f);

    #pragma unroll
    for (int j = 0; j < 8; j++) {
        int e = lane * 4 + j * 128;
        float4 gv = *(const float4*)(g + e);
        float4 bv = *(const float4*)(beta + e);
        float4 o;
        o.x = (xv[j].x - mean) * rstd * gv.x + bv.x;
        o.y = (xv[j].y - mean) * rstd * gv.y + bv.y;
        o.z = (xv[j].z - mean) * rstd * gv.z + bv.z;
        o.w = (xv[j].w - mean) * rstd * gv.w + bv.w;
        *(float4*)(orow + e) = o;
        uint2 u;
        u.x = f22h(o.x, o.y);
        u.y = f22h(o.z, o.w);
        *(uint2*)(ohrow + e) = u;
    }
}

// ---------------------------------------------------------------------------
// Launch (second stream for deferred weight transposes, fork/join via events)
// ---------------------------------------------------------------------------
extern "C" void kernel_launch(void* const* d_in, const int* in_sizes, int n_in,
                              void* d_out, int out_size)
{
    const int*   x    = (const int*)  d_in[0];
    const float* emb  = (const float*)d_in[1];
    const float* Wq   = (const float*)d_in[2];
    const float* bq   = (const float*)d_in[3];
    const float* Wk   = (const float*)d_in[4];
    const float* bk   = (const float*)d_in[5];
    const float* Wv   = (const float*)d_in[6];
    const float* bv   = (const float*)d_in[7];
    const float* Wo   = (const float*)d_in[8];
    const float* bo   = (const float*)d_in[9];
    const float* ln1g = (const float*)d_in[10];
    const float* ln1b = (const float*)d_in[11];
    const float* ln2g = (const float*)d_in[12];
    const float* ln2b = (const float*)d_in[13];
    const float* W1   = (const float*)d_in[14];
    const float* b1   = (const float*)d_in[15];
    const float* W2   = (const float*)d_in[16];
    const float* b2   = (const float*)d_in[17];
    const float* Wout = (const float*)d_in[18];
    const float* bout = (const float*)d_in[19];
    float* out = (float*)d_out;

    float *act, *tmp, *hbuf, *bqkv;
    __half *act_h, *qkv_h, *attn_h, *h_h, *ff_h, *wh;
    cudaGetSymbolAddress((void**)&act,    g_act);
    cudaGetSymbolAddress((void**)&act_h,  g_act_h);
    cudaGetSymbolAddress((void**)&qkv_h,  g_qkv_h);
    cudaGetSymbolAddress((void**)&attn_h, g_attn_h);
    cudaGetSymbolAddress((void**)&tmp,    g_tmp);
    cudaGetSymbolAddress((void**)&hbuf,   g_h);
    cudaGetSymbolAddress((void**)&h_h,    g_h_h);
    cudaGetSymbolAddress((void**)&ff_h,   g_ff_h);
    cudaGetSymbolAddress((void**)&bqkv,   g_bqkv);
    cudaGetSymbolAddress((void**)&wh,     g_wh);

    static int init_done = 0;
    static cudaStream_t s2;
    static cudaEvent_t evFork, evW12, evWout;
    if (!init_done) {
        cudaFuncSetAttribute(flash_attn_h,
                             cudaFuncAttributeMaxDynamicSharedMemorySize, ATTN_SMEM);
        cudaFuncSetAttribute(hgemm5<0, 0, 1, 0>,
                             cudaFuncAttributeMaxDynamicSharedMemorySize, GEMM_SMEM);
        cudaFuncSetAttribute(hgemm5<1, 0, 1, 0>,
                             cudaFuncAttributeMaxDynamicSharedMemorySize, GEMM_SMEM);
        cudaFuncSetAttribute(hgemm5<0, 1, 0, 1>,
                             cudaFuncAttributeMaxDynamicSharedMemorySize, GEMM_SMEM);
        cudaFuncSetAttribute(hgemm5<0, 1, 0, 0>,
                             cudaFuncAttributeMaxDynamicSharedMemorySize, GEMM_SMEM);
        cudaStreamCreateWithFlags(&s2, cudaStreamNonBlocking);
        cudaEventCreateWithFlags(&evFork, cudaEventDisableTiming);
        cudaEventCreateWithFlags(&evW12,  cudaEventDisableTiming);
        cudaEventCreateWithFlags(&evWout, cudaEventDisableTiming);
        init_done = 1;
    }

    dim3 tblk(16, 16);

    // ---- fork: deferred transposes (W1, W2, Wout) on stream s2 ----
    cudaEventRecord(evFork, 0);
    cudaStreamWaitEvent(s2, evFork, 0);
    {
        dim3 gW1(FF_DIM / 64, E_DIM / 64, L_NUM);
        transpose_half_b4<<<gW1, tblk, 0, s2>>>(W1, wh + OFF_W1, E_DIM, FF_DIM,
                                                (size_t)E_DIM * FF_DIM, W1_LSTR);
        dim3 gW2(E_DIM / 64, FF_DIM / 64, L_NUM);
        transpose_half_b4<<<gW2, tblk, 0, s2>>>(W2, wh + OFF_W2, FF_DIM, E_DIM,
                                                (size_t)FF_DIM * E_DIM, W2_LSTR);
        cudaEventRecord(evW12, s2);
        dim3 gWV(V_DIM / 64, E_DIM / 64, 1);
        transpose_half_b4<<<gWV, tblk, 0, s2>>>(Wout, wh + OFF_WOUT, E_DIM, V_DIM,
                                                (size_t)E_DIM * V_DIM, 0);
        cudaEventRecord(evWout, s2);
    }

    // ---- main stream: immediately-needed transposes + bias + embed ----
    {
        dim3 gEE(E_DIM / 64, E_DIM / 64, L_NUM);
        transpose_half_b4<<<gEE, tblk>>>(Wq, wh + 0 * WO_LSTR, E_DIM, E_DIM,
                                         (size_t)E_DIM * E_DIM, QKV_LSTR);
        transpose_half_b4<<<gEE, tblk>>>(Wk, wh + 1 * WO_LSTR, E_DIM, E_DIM,
                                         (size_t)E_DIM * E_DIM, QKV_LSTR);
        transpose_half_b4<<<gEE, tblk>>>(Wv, wh + 2 * WO_LSTR, E_DIM, E_DIM,
                                         (size_t)E_DIM * E_DIM, QKV_LSTR);
        transpose_half_b4<<<gEE, tblk>>>(Wo, wh + OFF_WO, E_DIM, E_DIM,
                                         (size_t)E_DIM * E_DIM, WO_LSTR);
        pack_qkv_bias<<<(L_NUM * QKV_STR) / 256, 256>>>(bq, bk, bv, bqkv);
    }

    embed_kernel<<<M_TOK, 256>>>(x, emb, act, act_h);

    for (int i = 0; i < L_NUM; i++) {
        size_t bo_off = (size_t)i * E_DIM;

        hgemm5<0, 0, 1, 0><<<dim3(M_TOK / GBM, QKV_STR / GBN), 256, GEMM_SMEM>>>(
            act_h, wh + (size_t)i * QKV_LSTR, bqkv + (size_t)i * QKV_STR,
            (const float*)0, (float*)0, qkv_h, QKV_STR, E_DIM);

        flash_attn_h<<<dim3(S_LEN / 128, H_DIM, N_B), 256, ATTN_SMEM>>>(qkv_h, attn_h);

        hgemm5<0, 1, 0, 1><<<dim3(M_TOK / GBM, E_DIM / GBN), 256, GEMM_SMEM>>>(
            attn_h, wh + OFF_WO + (size_t)i * WO_LSTR, bo + bo_off,
            act, tmp, (__half*)0, E_DIM, E_DIM);

        ln_kernel<<<M_TOK / 8, 256>>>(tmp, ln1g + bo_off, ln1b + bo_off, hbuf, h_h);

        if (i == 0) cudaStreamWaitEvent(0, evW12, 0);   // join W1/W2 transposes

        hgemm5<1, 0, 1, 0><<<dim3(M_TOK / GBM, FF_DIM / GBN), 256, GEMM_SMEM>>>(
            h_h, wh + OFF_W1 + (size_t)i * W1_LSTR, b1 + (size_t)i * FF_DIM,
            (const float*)0, (float*)0, ff_h, FF_DIM, E_DIM);

        hgemm5<0, 1, 0, 1><<<dim3(M_TOK / GBM, E_DIM / GBN), 256, GEMM_SMEM>>>(
            ff_h, wh + OFF_W2 + (size_t)i * W2_LSTR, b2 + bo_off,
            hbuf, tmp, (__half*)0, E_DIM, FF_DIM);

        ln_kernel<<<M_TOK / 8, 256>>>(tmp, ln2g + bo_off, ln2b + bo_off, act, act_h);
    }

    cudaStreamWaitEvent(0, evWout, 0);   // join Wout transpose
    hgemm5<0, 1, 0, 0><<<dim3(M_TOK / GBM, V_DIM / GBN), 256, GEMM_SMEM>>>(
        act_h, wh + OFF_WOUT, bout, (const float*)0, out, (__half*)0, V_DIM, E_DIM);
}